// round 8
// baseline (speedup 1.0000x reference)
#include <cuda_runtime.h>
#include <cuda_bf16.h>
#include <math.h>
#include <stdint.h>

#define ORD  2048
#define INDIM 64
#define TLEN 4096
#define NC   256

typedef unsigned long long ull;
typedef __nv_bfloat16 bf16;

// ================= static device scratch (allocation-free) =================
__device__ bf16 g_Ah [ORD*ORD], g_Al [ORD*ORD];   // wa straight
__device__ bf16 g_ATh[ORD*ORD], g_ATl[ORD*ORD];   // wa transposed
__device__ bf16 g_Q2h[ORD*ORD], g_Q2l[ORD*ORD], g_Q2Th[ORD*ORD], g_Q2Tl[ORD*ORD];
__device__ bf16 g_Q4h[ORD*ORD], g_Q4l[ORD*ORD], g_Q4Th[ORD*ORD], g_Q4Tl[ORD*ORD];
__device__ bf16 g_Q8h[ORD*ORD], g_Q8l[ORD*ORD], g_Q8Th[ORD*ORD], g_Q8Tl[ORD*ORD];
__device__ float g_Q16[ORD*ORD];
__device__ float g_E0[ORD*4096];
__device__ bf16 g_E0Th[4096*ORD], g_E0Tl[4096*ORD];
__device__ float g_E1[ORD*2048];
__device__ bf16 g_E1Th[2048*ORD], g_E1Tl[2048*ORD];
__device__ float g_E2[ORD*1024];
__device__ bf16 g_E2Th[1024*ORD], g_E2Tl[1024*ORD];
__device__ float g_E3[ORD*512];
__device__ bf16 g_E3Th[512*ORD], g_E3Tl[512*ORD];
__device__ float g_D[ORD*256];
__device__ bf16 g_STh[4096*ORD], g_STl[4096*ORD];   // states transposed, row=j*256+c
__device__ float g_bv[2 * ORD];
__device__ unsigned int g_bar_count;
__device__ volatile unsigned int g_bar_gen;

// ================= helpers =================
__device__ __forceinline__ uint32_t smem_u32(const void* p) {
    return (uint32_t)__cvta_generic_to_shared(p);
}
// 64B-row swizzle: XOR 16B-group bits [5:4] with row bits (addr bits [8:7])
#define SWZ64(b) ((b) ^ (((b) >> 3) & 0x30))

__device__ __forceinline__ void cp16(uint32_t dst, const void* src) {
    asm volatile("cp.async.cg.shared.global [%0], [%1], 16;" :: "r"(dst), "l"(src));
}
__device__ __forceinline__ void cp_commit() {
    asm volatile("cp.async.commit_group;" ::: "memory");
}

__device__ __forceinline__ void ldm_x4(uint32_t* r, uint32_t addr) {
    asm volatile("ldmatrix.sync.aligned.m8n8.x4.shared.b16 {%0,%1,%2,%3}, [%4];"
        : "=r"(r[0]), "=r"(r[1]), "=r"(r[2]), "=r"(r[3]) : "r"(addr));
}
__device__ __forceinline__ void mma_bf16(float* d, const uint32_t* a, const uint32_t* b) {
    asm volatile(
        "mma.sync.aligned.m16n8k16.row.col.f32.bf16.bf16.f32 "
        "{%0,%1,%2,%3}, {%4,%5,%6,%7}, {%8,%9}, {%0,%1,%2,%3};"
        : "+f"(d[0]), "+f"(d[1]), "+f"(d[2]), "+f"(d[3])
        : "r"(a[0]), "r"(a[1]), "r"(a[2]), "r"(a[3]), "r"(b[0]), "r"(b[1]));
}

// ================= packed f32x2 helpers (scan kernel) =================
__device__ __forceinline__ ull fma2(ull a, ull b, ull c) {
    ull d;
    asm("fma.rn.f32x2 %0, %1, %2, %3;" : "=l"(d) : "l"(a), "l"(b), "l"(c));
    return d;
}
__device__ __forceinline__ float2 unpk(ull v) {
    float2 f;
    asm("mov.b64 {%0, %1}, %2;" : "=f"(f.x), "=f"(f.y) : "l"(v));
    return f;
}

// ================= single-wave spin grid barrier =================
__device__ __forceinline__ void grid_barrier(unsigned int nb) {
    __syncthreads();
    if (threadIdx.x == 0) {
        __threadfence();
        unsigned int gen = g_bar_gen;
        if (atomicAdd(&g_bar_count, 1u) == nb - 1u) {
            g_bar_count = 0u;
            __threadfence();
            g_bar_gen = gen + 1u;
        } else {
            while (g_bar_gen == gen) { __nanosleep(32); }
        }
        __threadfence();
    }
    __syncthreads();
}

// ================= conversion kernels =================
__global__ void conv_straight(const float* __restrict__ src,
                              bf16* __restrict__ h, bf16* __restrict__ l) {
    int idx = blockIdx.x * 256 + threadIdx.x;
    float v = src[idx];
    bf16 hi = __float2bfloat16(v);
    h[idx] = hi;
    l[idx] = __float2bfloat16(v - __bfloat162float(hi));
}

__global__ void conv_transpose(const float* __restrict__ src,
                               bf16* __restrict__ th, bf16* __restrict__ tl) {
    __shared__ float tile[32][33];
    int bx = blockIdx.x * 32, by = blockIdx.y * 32;
    int tx = threadIdx.x;
    for (int i = threadIdx.y; i < 32; i += 8)
        tile[i][tx] = src[(size_t)(by + i) * ORD + bx + tx];
    __syncthreads();
    for (int i = threadIdx.y; i < 32; i += 8) {
        float v = tile[tx][i];                  // = src[by+tx][bx+i]
        bf16 hi = __float2bfloat16(v);
        size_t o = (size_t)(bx + i) * ORD + by + tx;
        th[o] = hi;
        tl[o] = __float2bfloat16(v - __bfloat162float(hi));
    }
}

// ================= BU precompute =================
__global__ void bu_kernel(const float* __restrict__ B, const float* __restrict__ u,
                          float* __restrict__ E0,
                          bf16* __restrict__ E0Th, bf16* __restrict__ E0Tl) {
    int t = blockIdx.x * 32 + threadIdx.x;   // blockDim (32,8)
    int r = blockIdx.y * 8 + threadIdx.y;
    float s = 0.f;
#pragma unroll
    for (int d = 0; d < INDIM; d++)
        s += B[r * INDIM + d] * u[d * TLEN + t];
    size_t col = (size_t)(t & 15) * 256 + (t >> 4);
    E0[(size_t)r * 4096 + col] = s;
    bf16 hi = __float2bfloat16(s);
    E0Th[col * ORD + r] = hi;
    E0Tl[col * ORD + r] = __float2bfloat16(s - __bfloat162float(hi));
}

// ================= mma.sync GEMM =================
// D[m][n] = sum_k A[m][k]*BT[n][k], bf16 3-product split, fp32 accum.
// CTA tile M=128 x N=256 (one full 256-col logical block per CTA),
// warp tile 64x64 (8 warps, wm in {0,1}, wn in {0..3}) for 1.5x better
// FLOP per smem byte. 3-stage cp.async pipeline, one sync per iter.
#define KC 32
#define STG_B 49152            // Ah 8K | Al 8K | Bh 16K | Bl 16K
#define NSTG 3
#define GEMM_SMEM (NSTG * STG_B)  // 144KB; reused as float Cs[128][264] (135KB)

#define SOFF_AL 8192
#define SOFF_BH 16384
#define SOFF_BL 32768

__device__ __forceinline__ void load_stage(
    uint32_t st, const bf16* __restrict__ Ah, const bf16* __restrict__ Al,
    const bf16* __restrict__ Bh, const bf16* __restrict__ Bl,
    size_t arow0, size_t brow0, size_t kb, int tid)
{
#pragma unroll
    for (int q = 0; q < 2; q++) {
        int ch = tid + q * 256;
        int row = ch >> 2, kg = ch & 3;
        uint32_t p = SWZ64((uint32_t)(row * 64 + kg * 16));
        size_t go = (arow0 + row) * ORD + kb + kg * 8;
        cp16(st + p, Ah + go);
        cp16(st + SOFF_AL + p, Al + go);
    }
#pragma unroll
    for (int q = 0; q < 4; q++) {
        int ch = tid + q * 256;
        int row = ch >> 2, kg = ch & 3;
        uint32_t p = SWZ64((uint32_t)(row * 64 + kg * 16));
        size_t go = (brow0 + row) * ORD + kb + kg * 8;
        cp16(st + SOFF_BH + p, Bh + go);
        cp16(st + SOFF_BL + p, Bl + go);
    }
}

__global__ void __launch_bounds__(256, 1) gemm_mma(
    const bf16* __restrict__ Ah, const bf16* __restrict__ Al,
    const bf16* __restrict__ Bh, const bf16* __restrict__ Bl,
    int bmul, int boff,
    float* __restrict__ C, int ldc,
    bf16* __restrict__ Sh, bf16* __restrict__ Sl,
    bf16* __restrict__ Th, bf16* __restrict__ Tl,
    const float* __restrict__ E, int lde, int amul, int aoff,
    float* __restrict__ outp, int dmul, int doff)
{
    extern __shared__ char smem[];
    uint32_t sb = smem_u32(smem);
    int tid = threadIdx.x, wid = tid >> 5, lane = tid & 31;
    int bm = blockIdx.y * 128;
    int dblk = blockIdx.x;
    size_t arow0 = (size_t)bm;
    size_t brow0 = (size_t)(bmul * dblk + boff) * 256;
    int wm = wid >> 2, wn = wid & 3;

    float acc[4][8][4];
#pragma unroll
    for (int i = 0; i < 4; i++)
#pragma unroll
        for (int j = 0; j < 8; j++)
#pragma unroll
            for (int k = 0; k < 4; k++) acc[i][j][k] = 0.f;

    // precompute swizzled fragment addresses (stage-relative)
    uint32_t a_off[2][4], b_off[2][4];
#pragma unroll
    for (int k16 = 0; k16 < 2; k16++) {
#pragma unroll
        for (int mt = 0; mt < 4; mt++) {
            int row = wm * 64 + mt * 16 + (lane & 15);
            a_off[k16][mt] = SWZ64((uint32_t)(row * 64 + k16 * 32 + (lane >> 4) * 16));
        }
#pragma unroll
        for (int g = 0; g < 4; g++) {
            int n = wn * 64 + g * 16 + ((lane >> 4) & 1) * 8 + (lane & 7);
            b_off[k16][g] = SWZ64((uint32_t)(n * 64 + k16 * 32 + ((lane >> 3) & 1) * 16));
        }
    }

    // prologue: stages 0..1
#pragma unroll
    for (int s = 0; s < NSTG - 1; s++) {
        load_stage(sb + s * STG_B, Ah, Al, Bh, Bl, arow0, brow0, (size_t)s * KC, tid);
        cp_commit();
    }

    const int NIT = ORD / KC;   // 64
    int stage = 0;
    for (int t = 0; t < NIT; t++) {
        if (t < NIT - 1) asm volatile("cp.async.wait_group 1;" ::: "memory");
        else             asm volatile("cp.async.wait_group 0;" ::: "memory");
        __syncthreads();

        // issue next stage loads immediately (slot was consumed at iter t-1)
        if (t + NSTG - 1 < NIT) {
            int ns = stage + NSTG - 1; if (ns >= NSTG) ns -= NSTG;
            load_stage(sb + ns * STG_B, Ah, Al, Bh, Bl,
                       arow0, brow0, (size_t)(t + NSTG - 1) * KC, tid);
            cp_commit();
        }

        uint32_t st = sb + stage * STG_B;
#pragma unroll
        for (int k16 = 0; k16 < 2; k16++) {
            uint32_t ah[4][4], al[4][4], bh[4][4], bl[4][4];
#pragma unroll
            for (int mt = 0; mt < 4; mt++) {
                ldm_x4(ah[mt], st + a_off[k16][mt]);
                ldm_x4(al[mt], st + SOFF_AL + a_off[k16][mt]);
            }
#pragma unroll
            for (int g = 0; g < 4; g++) {
                ldm_x4(bh[g], st + SOFF_BH + b_off[k16][g]);
                ldm_x4(bl[g], st + SOFF_BL + b_off[k16][g]);
            }
#pragma unroll
            for (int mt = 0; mt < 4; mt++)
#pragma unroll
                for (int g = 0; g < 4; g++)
#pragma unroll
                    for (int h = 0; h < 2; h++) {
                        float* ac = acc[mt][g * 2 + h];
                        const uint32_t* bhp = &bh[g][h * 2];
                        const uint32_t* blp = &bl[g][h * 2];
                        mma_bf16(ac, ah[mt], bhp);
                        mma_bf16(ac, ah[mt], blp);
                        mma_bf16(ac, al[mt], bhp);
                    }
        }
        stage++; if (stage >= NSTG) stage = 0;
    }
    __syncthreads();   // all MMAs done before smem reuse as Cs

    // ---- epilogue: spill accumulators to padded smem ----
    float (*Cs)[264] = (float (*)[264])smem;
#pragma unroll
    for (int mt = 0; mt < 4; mt++)
#pragma unroll
        for (int nt = 0; nt < 8; nt++) {
            int r = wm * 64 + mt * 16 + (lane >> 2);
            int c = wn * 64 + (nt >> 1) * 16 + (nt & 1) * 8 + 2 * (lane & 3);
            *(float2*)&Cs[r][c]     = make_float2(acc[mt][nt][0], acc[mt][nt][1]);
            *(float2*)&Cs[r + 8][c] = make_float2(acc[mt][nt][2], acc[mt][nt][3]);
        }
    __syncthreads();

    int jdst = dmul * dblk + doff;
    // phase A: row-major outputs (2 threads per row, 128 cols each)
    {
        int row = tid >> 1, chb = (tid & 1) * 128;
        int m = bm + row;
#pragma unroll 1
        for (int cb = 0; cb < 8; cb++) {
            int c0 = chb + cb * 16;
            float v[16];
#pragma unroll
            for (int i = 0; i < 16; i++) v[i] = Cs[row][c0 + i];
            if (E) {
                const float* ep = E + (size_t)m * lde
                    + (size_t)(amul * dblk + aoff) * 256 + c0;
#pragma unroll
                for (int i = 0; i < 16; i += 4) {
                    float4 e4 = *(const float4*)(ep + i);
                    v[i] += e4.x; v[i+1] += e4.y; v[i+2] += e4.z; v[i+3] += e4.w;
                }
#pragma unroll
                for (int i = 0; i < 16; i++) Cs[row][c0 + i] = v[i];
            }
            if (C) {
                float* cp = C + (size_t)m * ldc + (size_t)jdst * 256 + c0;
#pragma unroll
                for (int i = 0; i < 16; i += 4)
                    *(float4*)(cp + i) = make_float4(v[i], v[i+1], v[i+2], v[i+3]);
            }
            if (Sh) {
                bf16* sp = Sh + (size_t)m * ORD + (size_t)jdst * 256 + c0;
                bf16* lp = Sl + (size_t)m * ORD + (size_t)jdst * 256 + c0;
#pragma unroll
                for (int i = 0; i < 16; i++) {
                    bf16 hi = __float2bfloat16(v[i]);
                    sp[i] = hi;
                    lp[i] = __float2bfloat16(v[i] - __bfloat162float(hi));
                }
            }
            if (outp) {
                float* op = outp + (size_t)m * TLEN + jdst;
#pragma unroll
                for (int i = 0; i < 16; i++)
                    op[(c0 + i) * 16] = tanhf(v[i]);
            }
        }
    }
    // phase B: transposed bf16-pair outputs (one column per thread)
    if (Th) {
        __syncthreads();
        int n = tid;
        size_t trow = (size_t)jdst * 256 + n;
        bf16* tp = Th + trow * ORD + bm;
        bf16* lp = Tl + trow * ORD + bm;
#pragma unroll 1
        for (int mb = 0; mb < 8; mb++) {
#pragma unroll
            for (int i = 0; i < 16; i++) {
                float vv = Cs[mb * 16 + i][n];
                bf16 hi = __float2bfloat16(vv);
                tp[mb * 16 + i] = hi;
                lp[mb * 16 + i] = __float2bfloat16(vv - __bfloat162float(hi));
            }
        }
    }
}

// ================= persistent boundary scan =================
// b_{c+1} = A16 b_c + D_c. Writes ST block 0 (bf16 pair, row=c, col=r) and tanh at t=c*16.
__global__ void __launch_bounds__(256, 1) scan_kernel(
    const float* __restrict__ A16, const float* __restrict__ D,
    bf16* __restrict__ STh, bf16* __restrict__ STl,
    float* __restrict__ outp)
{
    __shared__ float bs[ORD];
    __shared__ float red[16][9];

    int tid = threadIdx.x;
    int cta = blockIdx.x;                 // 128 CTAs, 16 rows each
    int rloc = tid & 15;
    int row = cta * 16 + rloc;
    int seg = (tid >> 4) * 128;

    ulonglong2 a2[32];
    const ulonglong2* Arow = (const ulonglong2*)(A16 + (size_t)row * ORD + seg);
#pragma unroll
    for (int i = 0; i < 32; i++) a2[i] = Arow[i];

    for (int i = tid; i < ORD; i += 256) g_bv[i] = 1.0f;
    if (tid < 16) {
        int rr = cta * 16 + tid;
        STh[rr] = __float2bfloat16(1.0f);
        STl[rr] = __float2bfloat16(0.0f);
        outp[(size_t)rr * TLEN] = tanhf(1.0f);
    }
    grid_barrier(128);

    for (int c = 0; c < NC - 1; c++) {
        const float4* bsrc = (const float4*)(g_bv + (c & 1) * ORD);
        float4* bdst4 = (float4*)bs;
        bdst4[tid] = bsrc[tid];
        bdst4[tid + 256] = bsrc[tid + 256];
        __syncthreads();

        ull pA = 0ull, pB = 0ull;
        const ulonglong2* b2 = (const ulonglong2*)(bs + seg);
#pragma unroll
        for (int i = 0; i < 32; i++) {
            pA = fma2(a2[i].x, b2[i].x, pA);
            pB = fma2(a2[i].y, b2[i].y, pB);
        }
        float2 fa = unpk(pA), fb = unpk(pB);
        float p = (fa.x + fa.y) + (fb.x + fb.y);
        p += __shfl_down_sync(0xffffffffu, p, 16);
        if ((tid & 31) < 16) red[rloc][tid >> 5] = p;
        __syncthreads();

        if (tid < 16) {
            int rr = cta * 16 + tid;
            float s = red[tid][0] + red[tid][1] + red[tid][2] + red[tid][3]
                    + red[tid][4] + red[tid][5] + red[tid][6] + red[tid][7]
                    + D[(size_t)rr * 256 + c];
            g_bv[((c + 1) & 1) * ORD + rr] = s;
            bf16 hi = __float2bfloat16(s);
            STh[(size_t)(c + 1) * ORD + rr] = hi;
            STl[(size_t)(c + 1) * ORD + rr] = __float2bfloat16(s - __bfloat162float(hi));
            outp[(size_t)rr * TLEN + (c + 1) * 16] = tanhf(s);
        }
        grid_barrier(128);
    }
}

// ================= host orchestration =================
extern "C" void kernel_launch(void* const* d_in, const int* in_sizes, int n_in,
                              void* d_out, int out_size) {
    const float* u = 0; const float* wa = 0; const float* wb = 0;
    for (int i = 0; i < n_in; i++) {
        if (in_sizes[i] == INDIM * TLEN)       u  = (const float*)d_in[i];
        else if (in_sizes[i] == ORD * ORD)     wa = (const float*)d_in[i];
        else if (in_sizes[i] == ORD * INDIM)   wb = (const float*)d_in[i];
    }
    float* out = (float*)d_out;

    bf16 *Ah, *Al, *ATh, *ATl;
    bf16 *Q2h, *Q2l, *Q2Th, *Q2Tl, *Q4h, *Q4l, *Q4Th, *Q4Tl;
    bf16 *Q8h, *Q8l, *Q8Th, *Q8Tl;
    bf16 *E0Th, *E0Tl, *E1Th, *E1Tl, *E2Th, *E2Tl, *E3Th, *E3Tl, *STh, *STl;
    float *Q16, *E0, *E1, *E2, *E3, *Dv;
    cudaGetSymbolAddress((void**)&Ah, g_Ah);   cudaGetSymbolAddress((void**)&Al, g_Al);
    cudaGetSymbolAddress((void**)&ATh, g_ATh); cudaGetSymbolAddress((void**)&ATl, g_ATl);
    cudaGetSymbolAddress((void**)&Q2h, g_Q2h); cudaGetSymbolAddress((void**)&Q2l, g_Q2l);
    cudaGetSymbolAddress((void**)&Q2Th, g_Q2Th); cudaGetSymbolAddress((void**)&Q2Tl, g_Q2Tl);
    cudaGetSymbolAddress((void**)&Q4h, g_Q4h); cudaGetSymbolAddress((void**)&Q4l, g_Q4l);
    cudaGetSymbolAddress((void**)&Q4Th, g_Q4Th); cudaGetSymbolAddress((void**)&Q4Tl, g_Q4Tl);
    cudaGetSymbolAddress((void**)&Q8h, g_Q8h); cudaGetSymbolAddress((void**)&Q8l, g_Q8l);
    cudaGetSymbolAddress((void**)&Q8Th, g_Q8Th); cudaGetSymbolAddress((void**)&Q8Tl, g_Q8Tl);
    cudaGetSymbolAddress((void**)&Q16, g_Q16);
    cudaGetSymbolAddress((void**)&E0, g_E0);
    cudaGetSymbolAddress((void**)&E0Th, g_E0Th); cudaGetSymbolAddress((void**)&E0Tl, g_E0Tl);
    cudaGetSymbolAddress((void**)&E1, g_E1);
    cudaGetSymbolAddress((void**)&E1Th, g_E1Th); cudaGetSymbolAddress((void**)&E1Tl, g_E1Tl);
    cudaGetSymbolAddress((void**)&E2, g_E2);
    cudaGetSymbolAddress((void**)&E2Th, g_E2Th); cudaGetSymbolAddress((void**)&E2Tl, g_E2Tl);
    cudaGetSymbolAddress((void**)&E3, g_E3);
    cudaGetSymbolAddress((void**)&E3Th, g_E3Th); cudaGetSymbolAddress((void**)&E3Tl, g_E3Tl);
    cudaGetSymbolAddress((void**)&Dv, g_D);
    cudaGetSymbolAddress((void**)&STh, g_STh); cudaGetSymbolAddress((void**)&STl, g_STl);

    cudaFuncSetAttribute(gemm_mma, cudaFuncAttributeMaxDynamicSharedMemorySize, GEMM_SMEM);

    // conversions of wa + BU precompute
    conv_straight<<<ORD * ORD / 256, 256>>>(wa, Ah, Al);
    conv_transpose<<<dim3(64, 64), dim3(32, 8)>>>(wa, ATh, ATl);
    bu_kernel<<<dim3(TLEN / 32, ORD / 8), dim3(32, 8)>>>(wb, u, E0, E0Th, E0Tl);

    // squarings: A^2, A^4, A^8, A^16
    gemm_mma<<<dim3(8, 16), 256, GEMM_SMEM>>>(Ah, Al, ATh, ATl, 1, 0,
        0, 0, Q2h, Q2l, Q2Th, Q2Tl, 0, 0, 0, 0, 0, 1, 0);
    gemm_mma<<<dim3(8, 16), 256, GEMM_SMEM>>>(Q2h, Q2l, Q2Th, Q2Tl, 1, 0,
        0, 0, Q4h, Q4l, Q4Th, Q4Tl, 0, 0, 0, 0, 0, 1, 0);
    gemm_mma<<<dim3(8, 16), 256, GEMM_SMEM>>>(Q4h, Q4l, Q4Th, Q4Tl, 1, 0,
        0, 0, Q8h, Q8l, Q8Th, Q8Tl, 0, 0, 0, 0, 0, 1, 0);
    gemm_mma<<<dim3(8, 16), 256, GEMM_SMEM>>>(Q8h, Q8l, Q8Th, Q8Tl, 1, 0,
        Q16, ORD, 0, 0, 0, 0, 0, 0, 0, 0, 0, 1, 0);

    // upsweep
    gemm_mma<<<dim3(8, 16), 256, GEMM_SMEM>>>(Ah, Al, E0Th, E0Tl, 2, 0,
        E1, 2048, 0, 0, E1Th, E1Tl, E0, 4096, 2, 1, 0, 1, 0);
    gemm_mma<<<dim3(4, 16), 256, GEMM_SMEM>>>(Q2h, Q2l, E1Th, E1Tl, 2, 0,
        E2, 1024, 0, 0, E2Th, E2Tl, E1, 2048, 2, 1, 0, 1, 0);
    gemm_mma<<<dim3(2, 16), 256, GEMM_SMEM>>>(Q4h, Q4l, E2Th, E2Tl, 2, 0,
        E3, 512, 0, 0, E3Th, E3Tl, E2, 1024, 2, 1, 0, 1, 0);
    gemm_mma<<<dim3(1, 16), 256, GEMM_SMEM>>>(Q8h, Q8l, E3Th, E3Tl, 2, 0,
        Dv, 256, 0, 0, 0, 0, E3, 512, 2, 1, 0, 1, 0);

    // serial boundary scan (emits j=0, fills ST block 0)
    scan_kernel<<<128, 256>>>(Q16, Dv, STh, STl, out);

    // downsweep
    gemm_mma<<<dim3(1, 16), 256, GEMM_SMEM>>>(Q8h, Q8l, STh, STl, 1, 0,
        0, 0, 0, 0, STh, STl, E3, 512, 2, 0, out, 0, 8);
    gemm_mma<<<dim3(2, 16), 256, GEMM_SMEM>>>(Q4h, Q4l, STh, STl, 8, 0,
        0, 0, 0, 0, STh, STl, E2, 1024, 2, 0, out, 8, 4);
    gemm_mma<<<dim3(4, 16), 256, GEMM_SMEM>>>(Q2h, Q2l, STh, STl, 4, 0,
        0, 0, 0, 0, STh, STl, E1, 2048, 2, 0, out, 4, 2);
    gemm_mma<<<dim3(8, 16), 256, GEMM_SMEM>>>(Ah, Al, STh, STl, 2, 0,
        0, 0, 0, 0, 0, 0, E0, 4096, 2, 0, out, 2, 1);
}

// round 9
// speedup vs baseline: 1.2506x; 1.2506x over previous
#include <cuda_runtime.h>
#include <cuda_bf16.h>
#include <math.h>
#include <stdint.h>

#define ORD  2048
#define INDIM 64
#define TLEN 4096
#define NC   256

typedef unsigned long long ull;
typedef __nv_bfloat16 bf16;

// ================= static device scratch (allocation-free) =================
__device__ bf16 g_Ah [ORD*ORD], g_Al [ORD*ORD];   // wa straight
__device__ bf16 g_ATh[ORD*ORD], g_ATl[ORD*ORD];   // wa transposed
__device__ bf16 g_Q2h[ORD*ORD], g_Q2l[ORD*ORD], g_Q2Th[ORD*ORD], g_Q2Tl[ORD*ORD];
__device__ bf16 g_Q4h[ORD*ORD], g_Q4l[ORD*ORD], g_Q4Th[ORD*ORD], g_Q4Tl[ORD*ORD];
__device__ bf16 g_Q8h[ORD*ORD], g_Q8l[ORD*ORD], g_Q8Th[ORD*ORD], g_Q8Tl[ORD*ORD];
__device__ float g_Q16[ORD*ORD];
__device__ float g_E0[ORD*4096];
__device__ bf16 g_E0Th[4096*ORD], g_E0Tl[4096*ORD];
__device__ float g_E1[ORD*2048];
__device__ bf16 g_E1Th[2048*ORD], g_E1Tl[2048*ORD];
__device__ float g_E2[ORD*1024];
__device__ bf16 g_E2Th[1024*ORD], g_E2Tl[1024*ORD];
__device__ float g_E3[ORD*512];
__device__ bf16 g_E3Th[512*ORD], g_E3Tl[512*ORD];
__device__ float g_D[ORD*256];
__device__ bf16 g_STh[4096*ORD], g_STl[4096*ORD];   // states transposed, row=j*256+c
__device__ float g_bv[2 * ORD];
__device__ unsigned int g_bar_count;
__device__ volatile unsigned int g_bar_gen;

// ================= helpers =================
__device__ __forceinline__ uint32_t smem_u32(const void* p) {
    return (uint32_t)__cvta_generic_to_shared(p);
}
// 64B-row swizzle: XOR 16B-group bits [5:4] with row bits (addr bits [8:7])
#define SWZ64(b) ((b) ^ (((b) >> 3) & 0x30))

__device__ __forceinline__ void cp16(uint32_t dst, const void* src) {
    asm volatile("cp.async.cg.shared.global [%0], [%1], 16;" :: "r"(dst), "l"(src));
}
__device__ __forceinline__ void cp_commit() {
    asm volatile("cp.async.commit_group;" ::: "memory");
}

__device__ __forceinline__ void ldm_x4(uint32_t* r, uint32_t addr) {
    asm volatile("ldmatrix.sync.aligned.m8n8.x4.shared.b16 {%0,%1,%2,%3}, [%4];"
        : "=r"(r[0]), "=r"(r[1]), "=r"(r[2]), "=r"(r[3]) : "r"(addr));
}
__device__ __forceinline__ void mma_bf16(float* d, const uint32_t* a, const uint32_t* b) {
    asm volatile(
        "mma.sync.aligned.m16n8k16.row.col.f32.bf16.bf16.f32 "
        "{%0,%1,%2,%3}, {%4,%5,%6,%7}, {%8,%9}, {%0,%1,%2,%3};"
        : "+f"(d[0]), "+f"(d[1]), "+f"(d[2]), "+f"(d[3])
        : "r"(a[0]), "r"(a[1]), "r"(a[2]), "r"(a[3]), "r"(b[0]), "r"(b[1]));
}

// ================= packed f32x2 helpers (scan kernel) =================
__device__ __forceinline__ ull fma2(ull a, ull b, ull c) {
    ull d;
    asm("fma.rn.f32x2 %0, %1, %2, %3;" : "=l"(d) : "l"(a), "l"(b), "l"(c));
    return d;
}
__device__ __forceinline__ float2 unpk(ull v) {
    float2 f;
    asm("mov.b64 {%0, %1}, %2;" : "=f"(f.x), "=f"(f.y) : "l"(v));
    return f;
}

// ================= single-wave spin grid barrier =================
__device__ __forceinline__ void grid_barrier(unsigned int nb) {
    __syncthreads();
    if (threadIdx.x == 0) {
        __threadfence();
        unsigned int gen = g_bar_gen;
        if (atomicAdd(&g_bar_count, 1u) == nb - 1u) {
            g_bar_count = 0u;
            __threadfence();
            g_bar_gen = gen + 1u;
        } else {
            while (g_bar_gen == gen) { __nanosleep(32); }
        }
        __threadfence();
    }
    __syncthreads();
}

// ================= conversion kernels =================
__global__ void conv_straight(const float* __restrict__ src,
                              bf16* __restrict__ h, bf16* __restrict__ l) {
    int idx = blockIdx.x * 256 + threadIdx.x;
    float v = src[idx];
    bf16 hi = __float2bfloat16(v);
    h[idx] = hi;
    l[idx] = __float2bfloat16(v - __bfloat162float(hi));
}

__global__ void conv_transpose(const float* __restrict__ src,
                               bf16* __restrict__ th, bf16* __restrict__ tl) {
    __shared__ float tile[32][33];
    int bx = blockIdx.x * 32, by = blockIdx.y * 32;
    int tx = threadIdx.x;
    for (int i = threadIdx.y; i < 32; i += 8)
        tile[i][tx] = src[(size_t)(by + i) * ORD + bx + tx];
    __syncthreads();
    for (int i = threadIdx.y; i < 32; i += 8) {
        float v = tile[tx][i];                  // = src[by+tx][bx+i]
        bf16 hi = __float2bfloat16(v);
        size_t o = (size_t)(bx + i) * ORD + by + tx;
        th[o] = hi;
        tl[o] = __float2bfloat16(v - __bfloat162float(hi));
    }
}

// ================= BU precompute =================
__global__ void bu_kernel(const float* __restrict__ B, const float* __restrict__ u,
                          float* __restrict__ E0,
                          bf16* __restrict__ E0Th, bf16* __restrict__ E0Tl) {
    int t = blockIdx.x * 32 + threadIdx.x;   // blockDim (32,8)
    int r = blockIdx.y * 8 + threadIdx.y;
    float s = 0.f;
#pragma unroll
    for (int d = 0; d < INDIM; d++)
        s += B[r * INDIM + d] * u[d * TLEN + t];
    size_t col = (size_t)(t & 15) * 256 + (t >> 4);
    E0[(size_t)r * 4096 + col] = s;
    bf16 hi = __float2bfloat16(s);
    E0Th[col * ORD + r] = hi;
    E0Tl[col * ORD + r] = __float2bfloat16(s - __bfloat162float(hi));
}

// ================= mma.sync GEMM (R7 tiling) as batched job kernel =========
// D[m][n] = sum_k A[m][k]*BT[n][k], bf16 3-product split, fp32 accum.
// CTA tile M=128 x N=128, warp tile 64x32, 3-stage cp.async pipeline,
// one sync per iter, 2 CTAs/SM. Two independent jobs can share one launch.
#define KC 32
#define STG_B 32768            // Ah 8K | Al 8K | Bh 8K | Bl 8K
#define NSTG 3
#define GEMM_SMEM (NSTG * STG_B)  // 96KB; reused as float Cs[128][132]

struct GemmJob {
    const bf16 *Ah, *Al, *Bh, *Bl;
    int bmul, boff;
    float* C; int ldc;
    bf16 *Sh, *Sl, *Th, *Tl;
    const float* E; int lde, amul, aoff;
    float* outp; int dmul, doff;
    int gx;    // x-tiles (128-col tiles); y-tiles fixed at 16
};

__device__ __forceinline__ void load_stage(
    uint32_t st, const bf16* __restrict__ Ah, const bf16* __restrict__ Al,
    const bf16* __restrict__ Bh, const bf16* __restrict__ Bl,
    size_t arow0, size_t brow0, size_t kb, int tid)
{
#pragma unroll
    for (int q = 0; q < 2; q++) {
        int ch = tid + q * 256;
        int row = ch >> 2, kg = ch & 3;
        uint32_t p = SWZ64((uint32_t)(row * 64 + kg * 16));
        size_t go = (arow0 + row) * ORD + kb + kg * 8;
        cp16(st + p, Ah + go);
        cp16(st + 8192 + p, Al + go);
    }
#pragma unroll
    for (int q = 0; q < 2; q++) {
        int ch = tid + q * 256;
        int row = ch >> 2, kg = ch & 3;
        uint32_t p = SWZ64((uint32_t)(row * 64 + kg * 16));
        size_t go = (brow0 + row) * ORD + kb + kg * 8;
        cp16(st + 16384 + p, Bh + go);
        cp16(st + 24576 + p, Bl + go);
    }
}

__device__ void gemm_body(const GemmJob& J, int bx, int by) {
    extern __shared__ char smem[];
    uint32_t sb = smem_u32(smem);
    int tid = threadIdx.x, wid = tid >> 5, lane = tid & 31;
    int bm = by * 128;
    int dblk = bx >> 1, w = (bx & 1) * 128;
    size_t arow0 = (size_t)bm;
    size_t brow0 = (size_t)(J.bmul * dblk + J.boff) * 256 + w;
    int wm = wid >> 2, wn = wid & 3;

    float acc[4][4][4];
#pragma unroll
    for (int i = 0; i < 4; i++)
#pragma unroll
        for (int j = 0; j < 4; j++)
#pragma unroll
            for (int k = 0; k < 4; k++) acc[i][j][k] = 0.f;

    uint32_t a_off[2][4], b_off[2][2];
#pragma unroll
    for (int k16 = 0; k16 < 2; k16++) {
#pragma unroll
        for (int mt = 0; mt < 4; mt++) {
            int row = wm * 64 + mt * 16 + (lane & 15);
            a_off[k16][mt] = SWZ64((uint32_t)(row * 64 + k16 * 32 + (lane >> 4) * 16));
        }
#pragma unroll
        for (int p = 0; p < 2; p++) {
            int n = wn * 32 + p * 16 + ((lane >> 4) & 1) * 8 + (lane & 7);
            b_off[k16][p] = SWZ64((uint32_t)(n * 64 + k16 * 32 + ((lane >> 3) & 1) * 16));
        }
    }

#pragma unroll
    for (int s = 0; s < NSTG - 1; s++) {
        load_stage(sb + s * STG_B, J.Ah, J.Al, J.Bh, J.Bl,
                   arow0, brow0, (size_t)s * KC, tid);
        cp_commit();
    }

    const int NIT = ORD / KC;   // 64
    int stage = 0;
    for (int t = 0; t < NIT; t++) {
        if (t < NIT - 1) asm volatile("cp.async.wait_group 1;" ::: "memory");
        else             asm volatile("cp.async.wait_group 0;" ::: "memory");
        __syncthreads();

        if (t + NSTG - 1 < NIT) {
            int ns = stage + NSTG - 1; if (ns >= NSTG) ns -= NSTG;
            load_stage(sb + ns * STG_B, J.Ah, J.Al, J.Bh, J.Bl,
                       arow0, brow0, (size_t)(t + NSTG - 1) * KC, tid);
            cp_commit();
        }

        uint32_t st = sb + stage * STG_B;
#pragma unroll
        for (int k16 = 0; k16 < 2; k16++) {
            uint32_t ah[4][4], al[4][4], bh[2][4], bl[2][4];
#pragma unroll
            for (int mt = 0; mt < 4; mt++) {
                ldm_x4(ah[mt], st + a_off[k16][mt]);
                ldm_x4(al[mt], st + 8192 + a_off[k16][mt]);
            }
#pragma unroll
            for (int p = 0; p < 2; p++) {
                ldm_x4(bh[p], st + 16384 + b_off[k16][p]);
                ldm_x4(bl[p], st + 24576 + b_off[k16][p]);
            }
#pragma unroll
            for (int mt = 0; mt < 4; mt++)
#pragma unroll
                for (int nt = 0; nt < 4; nt++) {
                    const uint32_t* bhp = &bh[nt >> 1][(nt & 1) * 2];
                    const uint32_t* blp = &bl[nt >> 1][(nt & 1) * 2];
                    mma_bf16(acc[mt][nt], ah[mt], bhp);
                    mma_bf16(acc[mt][nt], ah[mt], blp);
                    mma_bf16(acc[mt][nt], al[mt], bhp);
                }
        }
        stage++; if (stage >= NSTG) stage = 0;
    }
    __syncthreads();   // all MMAs done before smem reuse as Cs

    float (*Cs)[132] = (float (*)[132])smem;
#pragma unroll
    for (int mt = 0; mt < 4; mt++)
#pragma unroll
        for (int nt = 0; nt < 4; nt++) {
            int r = wm * 64 + mt * 16 + (lane >> 2);
            int c = wn * 32 + nt * 8 + 2 * (lane & 3);
            *(float2*)&Cs[r][c]     = make_float2(acc[mt][nt][0], acc[mt][nt][1]);
            *(float2*)&Cs[r + 8][c] = make_float2(acc[mt][nt][2], acc[mt][nt][3]);
        }
    __syncthreads();

    int jdst = J.dmul * dblk + J.doff;
    {
        int row = tid >> 1, chb = (tid & 1) * 64;
        int m = bm + row;
#pragma unroll 1
        for (int cb = 0; cb < 4; cb++) {
            int c0 = chb + cb * 16;
            float v[16];
#pragma unroll
            for (int i = 0; i < 16; i++) v[i] = Cs[row][c0 + i];
            if (J.E) {
                const float* ep = J.E + (size_t)m * J.lde
                    + (size_t)(J.amul * dblk + J.aoff) * 256 + w + c0;
#pragma unroll
                for (int i = 0; i < 16; i += 4) {
                    float4 e4 = *(const float4*)(ep + i);
                    v[i] += e4.x; v[i+1] += e4.y; v[i+2] += e4.z; v[i+3] += e4.w;
                }
#pragma unroll
                for (int i = 0; i < 16; i++) Cs[row][c0 + i] = v[i];
            }
            if (J.C) {
                float* cp = J.C + (size_t)m * J.ldc + (size_t)jdst * 256 + w + c0;
#pragma unroll
                for (int i = 0; i < 16; i += 4)
                    *(float4*)(cp + i) = make_float4(v[i], v[i+1], v[i+2], v[i+3]);
            }
            if (J.Sh) {
                bf16* sp = J.Sh + (size_t)m * ORD + (size_t)jdst * 256 + w + c0;
                bf16* lp = J.Sl + (size_t)m * ORD + (size_t)jdst * 256 + w + c0;
#pragma unroll
                for (int i = 0; i < 16; i++) {
                    bf16 hi = __float2bfloat16(v[i]);
                    sp[i] = hi;
                    lp[i] = __float2bfloat16(v[i] - __bfloat162float(hi));
                }
            }
            if (J.outp) {
                float* op = J.outp + (size_t)m * TLEN + jdst;
#pragma unroll
                for (int i = 0; i < 16; i++)
                    op[(w + c0 + i) * 16] = tanhf(v[i]);
            }
        }
    }
    if (J.Th) {
        __syncthreads();
        int n = tid >> 1, mh = (tid & 1) * 64;
        size_t trow = (size_t)jdst * 256 + w + n;
        bf16* tp = J.Th + trow * ORD + bm + mh;
        bf16* lp = J.Tl + trow * ORD + bm + mh;
#pragma unroll 1
        for (int cb = 0; cb < 4; cb++) {
#pragma unroll
            for (int i = 0; i < 16; i++) {
                float vv = Cs[mh + cb * 16 + i][n];
                bf16 hi = __float2bfloat16(vv);
                tp[cb * 16 + i] = hi;
                lp[cb * 16 + i] = __float2bfloat16(vv - __bfloat162float(hi));
            }
        }
    }
}

__global__ void __launch_bounds__(256, 2) gemm_batch(GemmJob j0, GemmJob j1, int n0) {
    int bid = blockIdx.x;
    if (bid < n0) {
        gemm_body(j0, bid % j0.gx, bid / j0.gx);
    } else {
        int lid = bid - n0;
        gemm_body(j1, lid % j1.gx, lid / j1.gx);
    }
}

// ================= persistent boundary scan =================
// b_{c+1} = A16 b_c + D_c. Writes ST block 0 (bf16 pair, row=c, col=r) and tanh at t=c*16.
__global__ void __launch_bounds__(256, 1) scan_kernel(
    const float* __restrict__ A16, const float* __restrict__ D,
    bf16* __restrict__ STh, bf16* __restrict__ STl,
    float* __restrict__ outp)
{
    __shared__ float bs[ORD];
    __shared__ float red[16][9];

    int tid = threadIdx.x;
    int cta = blockIdx.x;                 // 128 CTAs, 16 rows each
    int rloc = tid & 15;
    int row = cta * 16 + rloc;
    int seg = (tid >> 4) * 128;

    ulonglong2 a2[32];
    const ulonglong2* Arow = (const ulonglong2*)(A16 + (size_t)row * ORD + seg);
#pragma unroll
    for (int i = 0; i < 32; i++) a2[i] = Arow[i];

    for (int i = tid; i < ORD; i += 256) g_bv[i] = 1.0f;
    if (tid < 16) {
        int rr = cta * 16 + tid;
        STh[rr] = __float2bfloat16(1.0f);
        STl[rr] = __float2bfloat16(0.0f);
        outp[(size_t)rr * TLEN] = tanhf(1.0f);
    }
    grid_barrier(128);

    for (int c = 0; c < NC - 1; c++) {
        const float4* bsrc = (const float4*)(g_bv + (c & 1) * ORD);
        float4* bdst4 = (float4*)bs;
        bdst4[tid] = bsrc[tid];
        bdst4[tid + 256] = bsrc[tid + 256];
        __syncthreads();

        ull pA = 0ull, pB = 0ull;
        const ulonglong2* b2 = (const ulonglong2*)(bs + seg);
#pragma unroll
        for (int i = 0; i < 32; i++) {
            pA = fma2(a2[i].x, b2[i].x, pA);
            pB = fma2(a2[i].y, b2[i].y, pB);
        }
        float2 fa = unpk(pA), fb = unpk(pB);
        float p = (fa.x + fa.y) + (fb.x + fb.y);
        p += __shfl_down_sync(0xffffffffu, p, 16);
        if ((tid & 31) < 16) red[rloc][tid >> 5] = p;
        __syncthreads();

        if (tid < 16) {
            int rr = cta * 16 + tid;
            float s = red[tid][0] + red[tid][1] + red[tid][2] + red[tid][3]
                    + red[tid][4] + red[tid][5] + red[tid][6] + red[tid][7]
                    + D[(size_t)rr * 256 + c];
            g_bv[((c + 1) & 1) * ORD + rr] = s;
            bf16 hi = __float2bfloat16(s);
            STh[(size_t)(c + 1) * ORD + rr] = hi;
            STl[(size_t)(c + 1) * ORD + rr] = __float2bfloat16(s - __bfloat162float(hi));
            outp[(size_t)rr * TLEN + (c + 1) * 16] = tanhf(s);
        }
        grid_barrier(128);
    }
}

// ================= host orchestration =================
static GemmJob mkjob(const bf16* Ah, const bf16* Al, const bf16* Bh, const bf16* Bl,
                     int bmul, int boff, float* C, int ldc,
                     bf16* Sh, bf16* Sl, bf16* Th, bf16* Tl,
                     const float* E, int lde, int amul, int aoff,
                     float* outp, int dmul, int doff, int gx) {
    GemmJob j;
    j.Ah = Ah; j.Al = Al; j.Bh = Bh; j.Bl = Bl;
    j.bmul = bmul; j.boff = boff; j.C = C; j.ldc = ldc;
    j.Sh = Sh; j.Sl = Sl; j.Th = Th; j.Tl = Tl;
    j.E = E; j.lde = lde; j.amul = amul; j.aoff = aoff;
    j.outp = outp; j.dmul = dmul; j.doff = doff; j.gx = gx;
    return j;
}

extern "C" void kernel_launch(void* const* d_in, const int* in_sizes, int n_in,
                              void* d_out, int out_size) {
    const float* u = 0; const float* wa = 0; const float* wb = 0;
    for (int i = 0; i < n_in; i++) {
        if (in_sizes[i] == INDIM * TLEN)       u  = (const float*)d_in[i];
        else if (in_sizes[i] == ORD * ORD)     wa = (const float*)d_in[i];
        else if (in_sizes[i] == ORD * INDIM)   wb = (const float*)d_in[i];
    }
    float* out = (float*)d_out;

    bf16 *Ah, *Al, *ATh, *ATl;
    bf16 *Q2h, *Q2l, *Q2Th, *Q2Tl, *Q4h, *Q4l, *Q4Th, *Q4Tl;
    bf16 *Q8h, *Q8l, *Q8Th, *Q8Tl;
    bf16 *E0Th, *E0Tl, *E1Th, *E1Tl, *E2Th, *E2Tl, *E3Th, *E3Tl, *STh, *STl;
    float *Q16, *E0, *E1, *E2, *E3, *Dv;
    cudaGetSymbolAddress((void**)&Ah, g_Ah);   cudaGetSymbolAddress((void**)&Al, g_Al);
    cudaGetSymbolAddress((void**)&ATh, g_ATh); cudaGetSymbolAddress((void**)&ATl, g_ATl);
    cudaGetSymbolAddress((void**)&Q2h, g_Q2h); cudaGetSymbolAddress((void**)&Q2l, g_Q2l);
    cudaGetSymbolAddress((void**)&Q2Th, g_Q2Th); cudaGetSymbolAddress((void**)&Q2Tl, g_Q2Tl);
    cudaGetSymbolAddress((void**)&Q4h, g_Q4h); cudaGetSymbolAddress((void**)&Q4l, g_Q4l);
    cudaGetSymbolAddress((void**)&Q4Th, g_Q4Th); cudaGetSymbolAddress((void**)&Q4Tl, g_Q4Tl);
    cudaGetSymbolAddress((void**)&Q8h, g_Q8h); cudaGetSymbolAddress((void**)&Q8l, g_Q8l);
    cudaGetSymbolAddress((void**)&Q8Th, g_Q8Th); cudaGetSymbolAddress((void**)&Q8Tl, g_Q8Tl);
    cudaGetSymbolAddress((void**)&Q16, g_Q16);
    cudaGetSymbolAddress((void**)&E0, g_E0);
    cudaGetSymbolAddress((void**)&E0Th, g_E0Th); cudaGetSymbolAddress((void**)&E0Tl, g_E0Tl);
    cudaGetSymbolAddress((void**)&E1, g_E1);
    cudaGetSymbolAddress((void**)&E1Th, g_E1Th); cudaGetSymbolAddress((void**)&E1Tl, g_E1Tl);
    cudaGetSymbolAddress((void**)&E2, g_E2);
    cudaGetSymbolAddress((void**)&E2Th, g_E2Th); cudaGetSymbolAddress((void**)&E2Tl, g_E2Tl);
    cudaGetSymbolAddress((void**)&E3, g_E3);
    cudaGetSymbolAddress((void**)&E3Th, g_E3Th); cudaGetSymbolAddress((void**)&E3Tl, g_E3Tl);
    cudaGetSymbolAddress((void**)&Dv, g_D);
    cudaGetSymbolAddress((void**)&STh, g_STh); cudaGetSymbolAddress((void**)&STl, g_STl);

    cudaFuncSetAttribute(gemm_batch, cudaFuncAttributeMaxDynamicSharedMemorySize, GEMM_SMEM);

    // conversions of wa + BU precompute
    conv_straight<<<ORD * ORD / 256, 256>>>(wa, Ah, Al);
    conv_transpose<<<dim3(64, 64), dim3(32, 8)>>>(wa, ATh, ATl);
    bu_kernel<<<dim3(TLEN / 32, ORD / 8), dim3(32, 8)>>>(wb, u, E0, E0Th, E0Tl);

    // jobs
    GemmJob jQ2  = mkjob(Ah, Al, ATh, ATl, 1, 0, 0, 0, Q2h, Q2l, Q2Th, Q2Tl,
                         0, 0, 0, 0, 0, 1, 0, 16);
    GemmJob jE1  = mkjob(Ah, Al, E0Th, E0Tl, 2, 0, E1, 2048, 0, 0, E1Th, E1Tl,
                         E0, 4096, 2, 1, 0, 1, 0, 16);
    GemmJob jQ4  = mkjob(Q2h, Q2l, Q2Th, Q2Tl, 1, 0, 0, 0, Q4h, Q4l, Q4Th, Q4Tl,
                         0, 0, 0, 0, 0, 1, 0, 16);
    GemmJob jE2  = mkjob(Q2h, Q2l, E1Th, E1Tl, 2, 0, E2, 1024, 0, 0, E2Th, E2Tl,
                         E1, 2048, 2, 1, 0, 1, 0, 8);
    GemmJob jQ8  = mkjob(Q4h, Q4l, Q4Th, Q4Tl, 1, 0, 0, 0, Q8h, Q8l, Q8Th, Q8Tl,
                         0, 0, 0, 0, 0, 1, 0, 16);
    GemmJob jE3  = mkjob(Q4h, Q4l, E2Th, E2Tl, 2, 0, E3, 512, 0, 0, E3Th, E3Tl,
                         E2, 1024, 2, 1, 0, 1, 0, 4);
    GemmJob jQ16 = mkjob(Q8h, Q8l, Q8Th, Q8Tl, 1, 0, Q16, ORD, 0, 0, 0, 0,
                         0, 0, 0, 0, 0, 1, 0, 16);
    GemmJob jD   = mkjob(Q8h, Q8l, E3Th, E3Tl, 2, 0, Dv, 256, 0, 0, 0, 0,
                         E3, 512, 2, 1, 0, 1, 0, 2);
    GemmJob jS8  = mkjob(Q8h, Q8l, STh, STl, 1, 0, 0, 0, 0, 0, STh, STl,
                         E3, 512, 2, 0, out, 0, 8, 2);
    GemmJob jS4  = mkjob(Q4h, Q4l, STh, STl, 8, 0, 0, 0, 0, 0, STh, STl,
                         E2, 1024, 2, 0, out, 8, 4, 4);
    GemmJob jS2  = mkjob(Q2h, Q2l, STh, STl, 4, 0, 0, 0, 0, 0, STh, STl,
                         E1, 2048, 2, 0, out, 4, 2, 8);
    GemmJob jS1  = mkjob(Ah, Al, STh, STl, 2, 0, 0, 0, 0, 0, 0, 0,
                         E0, 4096, 2, 0, out, 2, 1, 16);

    // level-batched: squaring chain || upsweep chain (independent within level)
    gemm_batch<<<256 + 256, 256, GEMM_SMEM>>>(jQ2, jE1, 256);
    gemm_batch<<<256 + 128, 256, GEMM_SMEM>>>(jQ4, jE2, 256);
    gemm_batch<<<256 + 64, 256, GEMM_SMEM>>>(jQ8, jE3, 256);
    gemm_batch<<<256 + 32, 256, GEMM_SMEM>>>(jQ16, jD, 256);

    // serial boundary scan (emits j=0, fills ST block 0)
    scan_kernel<<<128, 256>>>(Q16, Dv, STh, STl, out);

    // downsweep (strict serial chain)
    gemm_batch<<<32, 256, GEMM_SMEM>>>(jS8, jS8, 32);
    gemm_batch<<<64, 256, GEMM_SMEM>>>(jS4, jS4, 64);
    gemm_batch<<<128, 256, GEMM_SMEM>>>(jS2, jS2, 128);
    gemm_batch<<<256, 256, GEMM_SMEM>>>(jS1, jS1, 256);
}

// round 10
// speedup vs baseline: 1.2892x; 1.0308x over previous
#include <cuda_runtime.h>
#include <cuda_bf16.h>
#include <math.h>
#include <stdint.h>

#define ORD  2048
#define INDIM 64
#define TLEN 4096
#define NC   256

typedef unsigned long long ull;
typedef __nv_bfloat16 bf16;

// ================= static device scratch (allocation-free) =================
__device__ bf16 g_Ah [ORD*ORD], g_Al [ORD*ORD];   // wa straight
__device__ bf16 g_ATh[ORD*ORD], g_ATl[ORD*ORD];   // wa transposed
__device__ bf16 g_Q2h[ORD*ORD], g_Q2l[ORD*ORD], g_Q2Th[ORD*ORD], g_Q2Tl[ORD*ORD];
__device__ bf16 g_Q4h[ORD*ORD], g_Q4l[ORD*ORD], g_Q4Th[ORD*ORD], g_Q4Tl[ORD*ORD];
__device__ bf16 g_Q8h[ORD*ORD], g_Q8l[ORD*ORD], g_Q8Th[ORD*ORD], g_Q8Tl[ORD*ORD];
__device__ float g_Q16[ORD*ORD];
__device__ float g_E0[ORD*4096];
__device__ bf16 g_E0Th[4096*ORD], g_E0Tl[4096*ORD];
__device__ float g_E1[ORD*2048];
__device__ bf16 g_E1Th[2048*ORD], g_E1Tl[2048*ORD];
__device__ float g_E2[ORD*1024];
__device__ bf16 g_E2Th[1024*ORD], g_E2Tl[1024*ORD];
__device__ float g_E3[ORD*512];
__device__ bf16 g_E3Th[512*ORD], g_E3Tl[512*ORD];
__device__ float g_D[ORD*256];
__device__ bf16 g_STh[4096*ORD], g_STl[4096*ORD];   // states transposed, row=j*256+c
__device__ float g_part[8 * ORD * 256];              // 16MB split-K partials
__device__ float g_bv[2 * ORD];
__device__ unsigned int g_bar_count;
__device__ volatile unsigned int g_bar_gen;
__device__ volatile unsigned int g_flags[128];
__device__ volatile unsigned int g_gen2;

// ================= helpers =================
__device__ __forceinline__ uint32_t smem_u32(const void* p) {
    return (uint32_t)__cvta_generic_to_shared(p);
}
// 64B-row swizzle: XOR 16B-group bits [5:4] with row bits (addr bits [8:7])
#define SWZ64(b) ((b) ^ (((b) >> 3) & 0x30))

__device__ __forceinline__ void cp16(uint32_t dst, const void* src) {
    asm volatile("cp.async.cg.shared.global [%0], [%1], 16;" :: "r"(dst), "l"(src));
}
__device__ __forceinline__ void cp_commit() {
    asm volatile("cp.async.commit_group;" ::: "memory");
}

__device__ __forceinline__ void ldm_x4(uint32_t* r, uint32_t addr) {
    asm volatile("ldmatrix.sync.aligned.m8n8.x4.shared.b16 {%0,%1,%2,%3}, [%4];"
        : "=r"(r[0]), "=r"(r[1]), "=r"(r[2]), "=r"(r[3]) : "r"(addr));
}
__device__ __forceinline__ void mma_bf16(float* d, const uint32_t* a, const uint32_t* b) {
    asm volatile(
        "mma.sync.aligned.m16n8k16.row.col.f32.bf16.bf16.f32 "
        "{%0,%1,%2,%3}, {%4,%5,%6,%7}, {%8,%9}, {%0,%1,%2,%3};"
        : "+f"(d[0]), "+f"(d[1]), "+f"(d[2]), "+f"(d[3])
        : "r"(a[0]), "r"(a[1]), "r"(a[2]), "r"(a[3]), "r"(b[0]), "r"(b[1]));
}

// ================= packed f32x2 helpers (scan kernel) =================
__device__ __forceinline__ ull fma2(ull a, ull b, ull c) {
    ull d;
    asm("fma.rn.f32x2 %0, %1, %2, %3;" : "=l"(d) : "l"(a), "l"(b), "l"(c));
    return d;
}
__device__ __forceinline__ float2 unpk(ull v) {
    float2 f;
    asm("mov.b64 {%0, %1}, %2;" : "=f"(f.x), "=f"(f.y) : "l"(v));
    return f;
}

// ================= legacy atomic grid barrier (used once for init) =========
__device__ __forceinline__ void grid_barrier(unsigned int nb) {
    __syncthreads();
    if (threadIdx.x == 0) {
        __threadfence();
        unsigned int gen = g_bar_gen;
        if (atomicAdd(&g_bar_count, 1u) == nb - 1u) {
            g_bar_count = 0u;
            __threadfence();
            g_bar_gen = gen + 1u;
        } else {
            while (g_bar_gen == gen) { __nanosleep(32); }
        }
        __threadfence();
    }
    __syncthreads();
}

// ================= conversion kernels =================
__global__ void conv_straight(const float* __restrict__ src,
                              bf16* __restrict__ h, bf16* __restrict__ l) {
    int idx = blockIdx.x * 256 + threadIdx.x;
    float v = src[idx];
    bf16 hi = __float2bfloat16(v);
    h[idx] = hi;
    l[idx] = __float2bfloat16(v - __bfloat162float(hi));
}

__global__ void conv_transpose(const float* __restrict__ src,
                               bf16* __restrict__ th, bf16* __restrict__ tl) {
    __shared__ float tile[32][33];
    int bx = blockIdx.x * 32, by = blockIdx.y * 32;
    int tx = threadIdx.x;
    for (int i = threadIdx.y; i < 32; i += 8)
        tile[i][tx] = src[(size_t)(by + i) * ORD + bx + tx];
    __syncthreads();
    for (int i = threadIdx.y; i < 32; i += 8) {
        float v = tile[tx][i];                  // = src[by+tx][bx+i]
        bf16 hi = __float2bfloat16(v);
        size_t o = (size_t)(bx + i) * ORD + by + tx;
        th[o] = hi;
        tl[o] = __float2bfloat16(v - __bfloat162float(hi));
    }
}

// ================= BU precompute =================
__global__ void bu_kernel(const float* __restrict__ B, const float* __restrict__ u,
                          float* __restrict__ E0,
                          bf16* __restrict__ E0Th, bf16* __restrict__ E0Tl) {
    int t = blockIdx.x * 32 + threadIdx.x;   // blockDim (32,8)
    int r = blockIdx.y * 8 + threadIdx.y;
    float s = 0.f;
#pragma unroll
    for (int d = 0; d < INDIM; d++)
        s += B[r * INDIM + d] * u[d * TLEN + t];
    size_t col = (size_t)(t & 15) * 256 + (t >> 4);
    E0[(size_t)r * 4096 + col] = s;
    bf16 hi = __float2bfloat16(s);
    E0Th[col * ORD + r] = hi;
    E0Tl[col * ORD + r] = __float2bfloat16(s - __bfloat162float(hi));
}

// ================= mma.sync GEMM (batched job kernel, optional split-K) ====
#define KC 32
#define STG_B 32768            // Ah 8K | Al 8K | Bh 8K | Bl 8K
#define NSTG 3
#define GEMM_SMEM (NSTG * STG_B)  // 96KB; reused as float Cs[128][132]

struct GemmJob {
    const bf16 *Ah, *Al, *Bh, *Bl;
    int bmul, boff;
    float* C; int ldc;
    bf16 *Sh, *Sl, *Th, *Tl;
    const float* E; int lde, amul, aoff;
    float* outp; int dmul, doff;
    int gx;      // x-tiles (128-col tiles); y-tiles fixed 16
    int kz;      // split-K factor (1 = none)
    float* part; // partials buffer when kz>1
};

__device__ __forceinline__ void load_stage(
    uint32_t st, const bf16* __restrict__ Ah, const bf16* __restrict__ Al,
    const bf16* __restrict__ Bh, const bf16* __restrict__ Bl,
    size_t arow0, size_t brow0, size_t kb, int tid)
{
#pragma unroll
    for (int q = 0; q < 2; q++) {
        int ch = tid + q * 256;
        int row = ch >> 2, kg = ch & 3;
        uint32_t p = SWZ64((uint32_t)(row * 64 + kg * 16));
        size_t go = (arow0 + row) * ORD + kb + kg * 8;
        cp16(st + p, Ah + go);
        cp16(st + 8192 + p, Al + go);
    }
#pragma unroll
    for (int q = 0; q < 2; q++) {
        int ch = tid + q * 256;
        int row = ch >> 2, kg = ch & 3;
        uint32_t p = SWZ64((uint32_t)(row * 64 + kg * 16));
        size_t go = (brow0 + row) * ORD + kb + kg * 8;
        cp16(st + 16384 + p, Bh + go);
        cp16(st + 24576 + p, Bl + go);
    }
}

__device__ void gemm_body(const GemmJob& J, int bx, int by, int z) {
    extern __shared__ char smem[];
    uint32_t sb = smem_u32(smem);
    int tid = threadIdx.x, wid = tid >> 5, lane = tid & 31;
    int bm = by * 128;
    int dblk = bx >> 1, w = (bx & 1) * 128;
    size_t arow0 = (size_t)bm;
    size_t brow0 = (size_t)(J.bmul * dblk + J.boff) * 256 + w;
    size_t kbase = (size_t)z * (ORD / J.kz);
    const int NIT = (ORD / KC) / J.kz;
    int wm = wid >> 2, wn = wid & 3;

    float acc[4][4][4];
#pragma unroll
    for (int i = 0; i < 4; i++)
#pragma unroll
        for (int j = 0; j < 4; j++)
#pragma unroll
            for (int k = 0; k < 4; k++) acc[i][j][k] = 0.f;

    uint32_t a_off[2][4], b_off[2][2];
#pragma unroll
    for (int k16 = 0; k16 < 2; k16++) {
#pragma unroll
        for (int mt = 0; mt < 4; mt++) {
            int row = wm * 64 + mt * 16 + (lane & 15);
            a_off[k16][mt] = SWZ64((uint32_t)(row * 64 + k16 * 32 + (lane >> 4) * 16));
        }
#pragma unroll
        for (int p = 0; p < 2; p++) {
            int n = wn * 32 + p * 16 + ((lane >> 4) & 1) * 8 + (lane & 7);
            b_off[k16][p] = SWZ64((uint32_t)(n * 64 + k16 * 32 + ((lane >> 3) & 1) * 16));
        }
    }

#pragma unroll
    for (int s = 0; s < NSTG - 1; s++) {
        load_stage(sb + s * STG_B, J.Ah, J.Al, J.Bh, J.Bl,
                   arow0, brow0, kbase + (size_t)s * KC, tid);
        cp_commit();
    }

    int stage = 0;
    for (int t = 0; t < NIT; t++) {
        if (t < NIT - 1) asm volatile("cp.async.wait_group 1;" ::: "memory");
        else             asm volatile("cp.async.wait_group 0;" ::: "memory");
        __syncthreads();

        if (t + NSTG - 1 < NIT) {
            int ns = stage + NSTG - 1; if (ns >= NSTG) ns -= NSTG;
            load_stage(sb + ns * STG_B, J.Ah, J.Al, J.Bh, J.Bl,
                       arow0, brow0, kbase + (size_t)(t + NSTG - 1) * KC, tid);
            cp_commit();
        }

        uint32_t st = sb + stage * STG_B;
#pragma unroll
        for (int k16 = 0; k16 < 2; k16++) {
            uint32_t ah[4][4], al[4][4], bh[2][4], bl[2][4];
#pragma unroll
            for (int mt = 0; mt < 4; mt++) {
                ldm_x4(ah[mt], st + a_off[k16][mt]);
                ldm_x4(al[mt], st + 8192 + a_off[k16][mt]);
            }
#pragma unroll
            for (int p = 0; p < 2; p++) {
                ldm_x4(bh[p], st + 16384 + b_off[k16][p]);
                ldm_x4(bl[p], st + 24576 + b_off[k16][p]);
            }
#pragma unroll
            for (int mt = 0; mt < 4; mt++)
#pragma unroll
                for (int nt = 0; nt < 4; nt++) {
                    const uint32_t* bhp = &bh[nt >> 1][(nt & 1) * 2];
                    const uint32_t* blp = &bl[nt >> 1][(nt & 1) * 2];
                    mma_bf16(acc[mt][nt], ah[mt], bhp);
                    mma_bf16(acc[mt][nt], ah[mt], blp);
                    mma_bf16(acc[mt][nt], al[mt], bhp);
                }
        }
        stage++; if (stage >= NSTG) stage = 0;
    }
    __syncthreads();   // all MMAs done before smem reuse as Cs

    float (*Cs)[132] = (float (*)[132])smem;
#pragma unroll
    for (int mt = 0; mt < 4; mt++)
#pragma unroll
        for (int nt = 0; nt < 4; nt++) {
            int r = wm * 64 + mt * 16 + (lane >> 2);
            int c = wn * 32 + nt * 8 + 2 * (lane & 3);
            *(float2*)&Cs[r][c]     = make_float2(acc[mt][nt][0], acc[mt][nt][1]);
            *(float2*)&Cs[r + 8][c] = make_float2(acc[mt][nt][2], acc[mt][nt][3]);
        }
    __syncthreads();

    if (J.kz > 1) {
        // raw fp32 partial write; reduce kernel applies the epilogue
        int row = tid >> 1, off = (tid & 1) * 64;
        int Nw = J.gx * 128;
        float* pp = J.part + ((size_t)z * ORD + bm + row) * Nw + bx * 128 + off;
#pragma unroll
        for (int i = 0; i < 64; i += 4) {
            float4 v4 = *(const float4*)&Cs[row][off + i];
            *(float4*)(pp + i) = v4;
        }
        return;
    }

    int jdst = J.dmul * dblk + J.doff;
    {
        int row = tid >> 1, chb = (tid & 1) * 64;
        int m = bm + row;
#pragma unroll 1
        for (int cb = 0; cb < 4; cb++) {
            int c0 = chb + cb * 16;
            float v[16];
#pragma unroll
            for (int i = 0; i < 16; i++) v[i] = Cs[row][c0 + i];
            if (J.E) {
                const float* ep = J.E + (size_t)m * J.lde
                    + (size_t)(J.amul * dblk + J.aoff) * 256 + w + c0;
#pragma unroll
                for (int i = 0; i < 16; i += 4) {
                    float4 e4 = *(const float4*)(ep + i);
                    v[i] += e4.x; v[i+1] += e4.y; v[i+2] += e4.z; v[i+3] += e4.w;
                }
#pragma unroll
                for (int i = 0; i < 16; i++) Cs[row][c0 + i] = v[i];
            }
            if (J.C) {
                float* cp = J.C + (size_t)m * J.ldc + (size_t)jdst * 256 + w + c0;
#pragma unroll
                for (int i = 0; i < 16; i += 4)
                    *(float4*)(cp + i) = make_float4(v[i], v[i+1], v[i+2], v[i+3]);
            }
            if (J.Sh) {
                bf16* sp = J.Sh + (size_t)m * ORD + (size_t)jdst * 256 + w + c0;
                bf16* lp = J.Sl + (size_t)m * ORD + (size_t)jdst * 256 + w + c0;
#pragma unroll
                for (int i = 0; i < 16; i++) {
                    bf16 hi = __float2bfloat16(v[i]);
                    sp[i] = hi;
                    lp[i] = __float2bfloat16(v[i] - __bfloat162float(hi));
                }
            }
            if (J.outp) {
                float* op = J.outp + (size_t)m * TLEN + jdst;
#pragma unroll
                for (int i = 0; i < 16; i++)
                    op[(w + c0 + i) * 16] = tanhf(v[i]);
            }
        }
    }
    if (J.Th) {
        __syncthreads();
        int n = tid >> 1, mh = (tid & 1) * 64;
        size_t trow = (size_t)jdst * 256 + w + n;
        bf16* tp = J.Th + trow * ORD + bm + mh;
        bf16* lp = J.Tl + trow * ORD + bm + mh;
#pragma unroll 1
        for (int cb = 0; cb < 4; cb++) {
#pragma unroll
            for (int i = 0; i < 16; i++) {
                float vv = Cs[mh + cb * 16 + i][n];
                bf16 hi = __float2bfloat16(vv);
                tp[cb * 16 + i] = hi;
                lp[cb * 16 + i] = __float2bfloat16(vv - __bfloat162float(hi));
            }
        }
    }
}

__global__ void __launch_bounds__(256, 2) gemm_batch(GemmJob j0, GemmJob j1, int n0) {
    int bid = blockIdx.x;
    const GemmJob& J = (bid < n0) ? j0 : j1;
    int lid = (bid < n0) ? bid : bid - n0;
    int bx = lid % J.gx;
    int r = lid / J.gx;
    gemm_body(J, bx, r & 15, r >> 4);
}

// ================= split-K reduce with fused downsweep epilogue ============
// part: kz slabs of [ORD rows x N cols]. For each element: sum slabs + E addend,
// write transposed bf16 pair (coalesced via smem transpose) + tanh emission.
__global__ void __launch_bounds__(256) reduce_ds(
    const float* __restrict__ part, int N, int kz,
    const float* __restrict__ E, int lde, int amul, int aoff,
    bf16* __restrict__ Th, bf16* __restrict__ Tl,
    float* __restrict__ outp, int dmul, int doff)
{
    __shared__ float ts[64][65];
    int bm = blockIdx.y * 64, bn = blockIdx.x * 64;
    int tid = threadIdx.x;
    int dblk = bn >> 8;
    int jdst = dmul * dblk + doff;

    int r = tid >> 2, c0 = (tid & 3) * 16;
    int m = bm + r;
    float v[16];
    {
        const float* ep = E + (size_t)m * lde + (size_t)(amul * dblk + aoff) * 256
                        + (bn & 255) + c0;
#pragma unroll
        for (int i = 0; i < 16; i += 4) {
            float4 e4 = *(const float4*)(ep + i);
            v[i] = e4.x; v[i+1] = e4.y; v[i+2] = e4.z; v[i+3] = e4.w;
        }
    }
    for (int z = 0; z < kz; z++) {
        const float* pp = part + ((size_t)z * ORD + m) * N + bn + c0;
#pragma unroll
        for (int i = 0; i < 16; i += 4) {
            float4 p4 = *(const float4*)(pp + i);
            v[i] += p4.x; v[i+1] += p4.y; v[i+2] += p4.z; v[i+3] += p4.w;
        }
    }
    {
        float* op = outp + (size_t)m * TLEN + jdst;
#pragma unroll
        for (int i = 0; i < 16; i++)
            op[((bn & 255) + c0 + i) * 16] = tanhf(v[i]);
    }
#pragma unroll
    for (int i = 0; i < 16; i++) ts[r][c0 + i] = v[i];
    __syncthreads();

    int cc = tid >> 2, r0 = (tid & 3) * 16;
    size_t trow = (size_t)jdst * 256 + (bn & 255) + cc;
    bf16* tp = Th + trow * ORD + bm + r0;
    bf16* lp = Tl + trow * ORD + bm + r0;
#pragma unroll
    for (int i = 0; i < 16; i++) {
        float vv = ts[r0 + i][cc];
        bf16 hi = __float2bfloat16(vv);
        tp[i] = hi;
        lp[i] = __float2bfloat16(vv - __bfloat162float(hi));
    }
}

// ================= persistent boundary scan =================
// b_{c+1} = A16 b_c + D_c. Contention-free flag barrier (no atomics in loop).
__global__ void __launch_bounds__(256, 1) scan_kernel(
    const float* __restrict__ A16, const float* __restrict__ D,
    bf16* __restrict__ STh, bf16* __restrict__ STl,
    float* __restrict__ outp)
{
    __shared__ float bs[ORD];
    __shared__ float red[16][9];

    int tid = threadIdx.x;
    int cta = blockIdx.x;                 // 128 CTAs, 16 rows each
    int rloc = tid & 15;
    int row = cta * 16 + rloc;
    int seg = (tid >> 4) * 128;

    ulonglong2 a2[32];
    const ulonglong2* Arow = (const ulonglong2*)(A16 + (size_t)row * ORD + seg);
#pragma unroll
    for (int i = 0; i < 32; i++) a2[i] = Arow[i];

    for (int i = tid; i < ORD; i += 256) g_bv[i] = 1.0f;
    if (tid < 16) {
        int rr = cta * 16 + tid;
        STh[rr] = __float2bfloat16(1.0f);
        STl[rr] = __float2bfloat16(0.0f);
        outp[(size_t)rr * TLEN] = tanhf(1.0f);
    }
    // reset flag-barrier state (replay-safe: published via legacy barrier)
    if (tid == 0) {
        g_flags[cta] = 0u;
        if (cta == 0) g_gen2 = 0u;
    }
    grid_barrier(128);

    for (int c = 0; c < NC - 1; c++) {
        const float4* bsrc = (const float4*)(g_bv + (c & 1) * ORD);
        float4* bdst4 = (float4*)bs;
        bdst4[tid] = bsrc[tid];
        bdst4[tid + 256] = bsrc[tid + 256];
        float dval = 0.f;
        if (tid < 16) dval = D[(size_t)(cta * 16 + tid) * 256 + c];
        __syncthreads();

        ull pA = 0ull, pB = 0ull;
        const ulonglong2* b2 = (const ulonglong2*)(bs + seg);
#pragma unroll
        for (int i = 0; i < 32; i++) {
            pA = fma2(a2[i].x, b2[i].x, pA);
            pB = fma2(a2[i].y, b2[i].y, pB);
        }
        float2 fa = unpk(pA), fb = unpk(pB);
        float p = (fa.x + fa.y) + (fb.x + fb.y);
        p += __shfl_down_sync(0xffffffffu, p, 16);
        if ((tid & 31) < 16) red[rloc][tid >> 5] = p;
        __syncthreads();

        if (tid < 16) {
            int rr = cta * 16 + tid;
            float s = red[tid][0] + red[tid][1] + red[tid][2] + red[tid][3]
                    + red[tid][4] + red[tid][5] + red[tid][6] + red[tid][7]
                    + dval;
            g_bv[((c + 1) & 1) * ORD + rr] = s;
            bf16 hi = __float2bfloat16(s);
            STh[(size_t)(c + 1) * ORD + rr] = hi;
            STl[(size_t)(c + 1) * ORD + rr] = __float2bfloat16(s - __bfloat162float(hi));
            outp[(size_t)rr * TLEN + (c + 1) * 16] = tanhf(s);
        }

        // ---- contention-free flag barrier ----
        unsigned int it = (unsigned int)(c + 1);
        __syncthreads();
        if (cta == 0) {
            if (tid >= 1 && tid < 128) {
                unsigned int fv;
                do { fv = g_flags[tid]; } while (fv < it);
            }
            __syncthreads();
            if (tid == 0) { __threadfence(); g_gen2 = it; __threadfence(); }
            __syncthreads();
        } else {
            if (tid == 0) {
                __threadfence();
                g_flags[cta] = it;
                unsigned int gv;
                do { __nanosleep(16); gv = g_gen2; } while (gv < it);
                __threadfence();
            }
            __syncthreads();
        }
    }
}

// ================= host orchestration =================
static GemmJob mkjob(const bf16* Ah, const bf16* Al, const bf16* Bh, const bf16* Bl,
                     int bmul, int boff, float* C, int ldc,
                     bf16* Sh, bf16* Sl, bf16* Th, bf16* Tl,
                     const float* E, int lde, int amul, int aoff,
                     float* outp, int dmul, int doff, int gx, int kz, float* part) {
    GemmJob j;
    j.Ah = Ah; j.Al = Al; j.Bh = Bh; j.Bl = Bl;
    j.bmul = bmul; j.boff = boff; j.C = C; j.ldc = ldc;
    j.Sh = Sh; j.Sl = Sl; j.Th = Th; j.Tl = Tl;
    j.E = E; j.lde = lde; j.amul = amul; j.aoff = aoff;
    j.outp = outp; j.dmul = dmul; j.doff = doff; j.gx = gx;
    j.kz = kz; j.part = part;
    return j;
}

extern "C" void kernel_launch(void* const* d_in, const int* in_sizes, int n_in,
                              void* d_out, int out_size) {
    const float* u = 0; const float* wa = 0; const float* wb = 0;
    for (int i = 0; i < n_in; i++) {
        if (in_sizes[i] == INDIM * TLEN)       u  = (const float*)d_in[i];
        else if (in_sizes[i] == ORD * ORD)     wa = (const float*)d_in[i];
        else if (in_sizes[i] == ORD * INDIM)   wb = (const float*)d_in[i];
    }
    float* out = (float*)d_out;

    bf16 *Ah, *Al, *ATh, *ATl;
    bf16 *Q2h, *Q2l, *Q2Th, *Q2Tl, *Q4h, *Q4l, *Q4Th, *Q4Tl;
    bf16 *Q8h, *Q8l, *Q8Th, *Q8Tl;
    bf16 *E0Th, *E0Tl, *E1Th, *E1Tl, *E2Th, *E2Tl, *E3Th, *E3Tl, *STh, *STl;
    float *Q16, *E0, *E1, *E2, *E3, *Dv, *Part;
    cudaGetSymbolAddress((void**)&Ah, g_Ah);   cudaGetSymbolAddress((void**)&Al, g_Al);
    cudaGetSymbolAddress((void**)&ATh, g_ATh); cudaGetSymbolAddress((void**)&ATl, g_ATl);
    cudaGetSymbolAddress((void**)&Q2h, g_Q2h); cudaGetSymbolAddress((void**)&Q2l, g_Q2l);
    cudaGetSymbolAddress((void**)&Q2Th, g_Q2Th); cudaGetSymbolAddress((void**)&Q2Tl, g_Q2Tl);
    cudaGetSymbolAddress((void**)&Q4h, g_Q4h); cudaGetSymbolAddress((void**)&Q4l, g_Q4l);
    cudaGetSymbolAddress((void**)&Q4Th, g_Q4Th); cudaGetSymbolAddress((void**)&Q4Tl, g_Q4Tl);
    cudaGetSymbolAddress((void**)&Q8h, g_Q8h); cudaGetSymbolAddress((void**)&Q8l, g_Q8l);
    cudaGetSymbolAddress((void**)&Q8Th, g_Q8Th); cudaGetSymbolAddress((void**)&Q8Tl, g_Q8Tl);
    cudaGetSymbolAddress((void**)&Q16, g_Q16);
    cudaGetSymbolAddress((void**)&E0, g_E0);
    cudaGetSymbolAddress((void**)&E0Th, g_E0Th); cudaGetSymbolAddress((void**)&E0Tl, g_E0Tl);
    cudaGetSymbolAddress((void**)&E1, g_E1);
    cudaGetSymbolAddress((void**)&E1Th, g_E1Th); cudaGetSymbolAddress((void**)&E1Tl, g_E1Tl);
    cudaGetSymbolAddress((void**)&E2, g_E2);
    cudaGetSymbolAddress((void**)&E2Th, g_E2Th); cudaGetSymbolAddress((void**)&E2Tl, g_E2Tl);
    cudaGetSymbolAddress((void**)&E3, g_E3);
    cudaGetSymbolAddress((void**)&E3Th, g_E3Th); cudaGetSymbolAddress((void**)&E3Tl, g_E3Tl);
    cudaGetSymbolAddress((void**)&Dv, g_D);
    cudaGetSymbolAddress((void**)&STh, g_STh); cudaGetSymbolAddress((void**)&STl, g_STl);
    cudaGetSymbolAddress((void**)&Part, g_part);

    cudaFuncSetAttribute(gemm_batch, cudaFuncAttributeMaxDynamicSharedMemorySize, GEMM_SMEM);

    // conversions of wa + BU precompute
    conv_straight<<<ORD * ORD / 256, 256>>>(wa, Ah, Al);
    conv_transpose<<<dim3(64, 64), dim3(32, 8)>>>(wa, ATh, ATl);
    bu_kernel<<<dim3(TLEN / 32, ORD / 8), dim3(32, 8)>>>(wb, u, E0, E0Th, E0Tl);

    // jobs
    GemmJob jQ2  = mkjob(Ah, Al, ATh, ATl, 1, 0, 0, 0, Q2h, Q2l, Q2Th, Q2Tl,
                         0, 0, 0, 0, 0, 1, 0, 16, 1, 0);
    GemmJob jE1  = mkjob(Ah, Al, E0Th, E0Tl, 2, 0, E1, 2048, 0, 0, E1Th, E1Tl,
                         E0, 4096, 2, 1, 0, 1, 0, 16, 1, 0);
    GemmJob jQ4  = mkjob(Q2h, Q2l, Q2Th, Q2Tl, 1, 0, 0, 0, Q4h, Q4l, Q4Th, Q4Tl,
                         0, 0, 0, 0, 0, 1, 0, 16, 1, 0);
    GemmJob jE2  = mkjob(Q2h, Q2l, E1Th, E1Tl, 2, 0, E2, 1024, 0, 0, E2Th, E2Tl,
                         E1, 2048, 2, 1, 0, 1, 0, 8, 1, 0);
    GemmJob jQ8  = mkjob(Q4h, Q4l, Q4Th, Q4Tl, 1, 0, 0, 0, Q8h, Q8l, Q8Th, Q8Tl,
                         0, 0, 0, 0, 0, 1, 0, 16, 1, 0);
    GemmJob jE3  = mkjob(Q4h, Q4l, E2Th, E2Tl, 2, 0, E3, 512, 0, 0, E3Th, E3Tl,
                         E2, 1024, 2, 1, 0, 1, 0, 4, 1, 0);
    GemmJob jQ16 = mkjob(Q8h, Q8l, Q8Th, Q8Tl, 1, 0, Q16, ORD, 0, 0, 0, 0,
                         0, 0, 0, 0, 0, 1, 0, 16, 1, 0);
    GemmJob jD   = mkjob(Q8h, Q8l, E3Th, E3Tl, 2, 0, Dv, 256, 0, 0, 0, 0,
                         E3, 512, 2, 1, 0, 1, 0, 2, 1, 0);
    // downsweep: S8/S4 split-K (partials + reduce), S2/S1 direct
    GemmJob jS8  = mkjob(Q8h, Q8l, STh, STl, 1, 0, 0, 0, 0, 0, 0, 0,
                         0, 0, 0, 0, 0, 0, 8, 2, 8, Part);
    GemmJob jS4  = mkjob(Q4h, Q4l, STh, STl, 8, 0, 0, 0, 0, 0, 0, 0,
                         0, 0, 0, 0, 0, 8, 4, 4, 4, Part);
    GemmJob jS2  = mkjob(Q2h, Q2l, STh, STl, 4, 0, 0, 0, 0, 0, STh, STl,
                         E1, 2048, 2, 0, out, 4, 2, 8, 1, 0);
    GemmJob jS1  = mkjob(Ah, Al, STh, STl, 2, 0, 0, 0, 0, 0, 0, 0,
                         E0, 4096, 2, 0, out, 2, 1, 16, 1, 0);

    // level-batched: squaring chain || upsweep chain (independent within level)
    gemm_batch<<<256 + 256, 256, GEMM_SMEM>>>(jQ2, jE1, 256);
    gemm_batch<<<256 + 128, 256, GEMM_SMEM>>>(jQ4, jE2, 256);
    gemm_batch<<<256 + 64, 256, GEMM_SMEM>>>(jQ8, jE3, 256);
    gemm_batch<<<256 + 32, 256, GEMM_SMEM>>>(jQ16, jD, 256);

    // serial boundary scan (emits j=0, fills ST block 0)
    scan_kernel<<<128, 256>>>(Q16, Dv, STh, STl, out);

    // downsweep (serial chain; narrow levels split-K + fused reduce)
    gemm_batch<<<256, 256, GEMM_SMEM>>>(jS8, jS8, 256);          // 2*16*8
    reduce_ds<<<dim3(4, 32), 256>>>(Part, 256, 8, E3, 512, 2, 0,
                                    STh, STl, out, 0, 8);
    gemm_batch<<<256, 256, GEMM_SMEM>>>(jS4, jS4, 256);          // 4*16*4
    reduce_ds<<<dim3(8, 32), 256>>>(Part, 512, 4, E2, 1024, 2, 0,
                                    STh, STl, out, 8, 4);
    gemm_batch<<<128, 256, GEMM_SMEM>>>(jS2, jS2, 128);
    gemm_batch<<<256, 256, GEMM_SMEM>>>(jS1, jS1, 256);
}

// round 11
// speedup vs baseline: 1.6416x; 1.2734x over previous
#include <cuda_runtime.h>
#include <cuda_fp16.h>
#include <math.h>
#include <stdint.h>

#define ORD  2048
#define INDIM 64
#define TLEN 4096
#define NC   256

typedef unsigned long long ull;
typedef __half hf;

// ================= static device scratch (allocation-free) =================
__device__ hf g_Ah [ORD*ORD], g_Al [ORD*ORD];   // wa straight (hi, lo)
__device__ hf g_ATh[ORD*ORD];                   // wa transposed (hi only)
__device__ hf g_Q2h[ORD*ORD], g_Q2l[ORD*ORD], g_Q2Th[ORD*ORD];
__device__ hf g_Q4h[ORD*ORD], g_Q4l[ORD*ORD], g_Q4Th[ORD*ORD];
__device__ hf g_Q8h[ORD*ORD], g_Q8l[ORD*ORD], g_Q8Th[ORD*ORD];
__device__ float g_Q16[ORD*ORD];
__device__ float g_E0[ORD*4096];
__device__ hf g_E0Th[4096*ORD];
__device__ float g_E1[ORD*2048];
__device__ hf g_E1Th[2048*ORD];
__device__ float g_E2[ORD*1024];
__device__ hf g_E2Th[1024*ORD];
__device__ float g_E3[ORD*512];
__device__ hf g_E3Th[512*ORD];
__device__ float g_D[ORD*256];
__device__ hf g_STh[4096*ORD];                  // states transposed, row=j*256+c
__device__ float g_part[8 * ORD * 256];         // 16MB split-K partials
__device__ float g_bv[2 * ORD];
__device__ unsigned int g_bar_count;
__device__ volatile unsigned int g_bar_gen;
__device__ volatile unsigned int g_flags[128];
__device__ volatile unsigned int g_gen2;

// ================= helpers =================
__device__ __forceinline__ uint32_t smem_u32(const void* p) {
    return (uint32_t)__cvta_generic_to_shared(p);
}
// 64B-row swizzle: XOR 16B-group bits [5:4] with row bits (addr bits [8:7])
#define SWZ64(b) ((b) ^ (((b) >> 3) & 0x30))

__device__ __forceinline__ void cp16(uint32_t dst, const void* src) {
    asm volatile("cp.async.cg.shared.global [%0], [%1], 16;" :: "r"(dst), "l"(src));
}
__device__ __forceinline__ void cp_commit() {
    asm volatile("cp.async.commit_group;" ::: "memory");
}

__device__ __forceinline__ void ldm_x4(uint32_t* r, uint32_t addr) {
    asm volatile("ldmatrix.sync.aligned.m8n8.x4.shared.b16 {%0,%1,%2,%3}, [%4];"
        : "=r"(r[0]), "=r"(r[1]), "=r"(r[2]), "=r"(r[3]) : "r"(addr));
}
__device__ __forceinline__ void mma_f16(float* d, const uint32_t* a, const uint32_t* b) {
    asm volatile(
        "mma.sync.aligned.m16n8k16.row.col.f32.f16.f16.f32 "
        "{%0,%1,%2,%3}, {%4,%5,%6,%7}, {%8,%9}, {%0,%1,%2,%3};"
        : "+f"(d[0]), "+f"(d[1]), "+f"(d[2]), "+f"(d[3])
        : "r"(a[0]), "r"(a[1]), "r"(a[2]), "r"(a[3]), "r"(b[0]), "r"(b[1]));
}

// ================= packed f32x2 helpers (scan kernel) =================
__device__ __forceinline__ ull fma2(ull a, ull b, ull c) {
    ull d;
    asm("fma.rn.f32x2 %0, %1, %2, %3;" : "=l"(d) : "l"(a), "l"(b), "l"(c));
    return d;
}
__device__ __forceinline__ float2 unpk(ull v) {
    float2 f;
    asm("mov.b64 {%0, %1}, %2;" : "=f"(f.x), "=f"(f.y) : "l"(v));
    return f;
}

// ================= legacy atomic grid barrier (used once for init) =========
__device__ __forceinline__ void grid_barrier(unsigned int nb) {
    __syncthreads();
    if (threadIdx.x == 0) {
        __threadfence();
        unsigned int gen = g_bar_gen;
        if (atomicAdd(&g_bar_count, 1u) == nb - 1u) {
            g_bar_count = 0u;
            __threadfence();
            g_bar_gen = gen + 1u;
        } else {
            while (g_bar_gen == gen) { __nanosleep(32); }
        }
        __threadfence();
    }
    __syncthreads();
}

// ================= conversion kernels =================
__global__ void conv_straight(const float* __restrict__ src,
                              hf* __restrict__ h, hf* __restrict__ l) {
    int idx = blockIdx.x * 256 + threadIdx.x;
    float v = src[idx];
    hf hi = __float2half_rn(v);
    h[idx] = hi;
    l[idx] = __float2half_rn(v - __half2float(hi));
}

__global__ void conv_transpose(const float* __restrict__ src,
                               hf* __restrict__ th) {
    __shared__ float tile[32][33];
    int bx = blockIdx.x * 32, by = blockIdx.y * 32;
    int tx = threadIdx.x;
    for (int i = threadIdx.y; i < 32; i += 8)
        tile[i][tx] = src[(size_t)(by + i) * ORD + bx + tx];
    __syncthreads();
    for (int i = threadIdx.y; i < 32; i += 8)
        th[(size_t)(bx + i) * ORD + by + tx] = __float2half_rn(tile[tx][i]);
}

// ================= BU precompute =================
__global__ void bu_kernel(const float* __restrict__ B, const float* __restrict__ u,
                          float* __restrict__ E0, hf* __restrict__ E0Th) {
    int t = blockIdx.x * 32 + threadIdx.x;   // blockDim (32,8)
    int r = blockIdx.y * 8 + threadIdx.y;
    float s = 0.f;
#pragma unroll
    for (int d = 0; d < INDIM; d++)
        s += B[r * INDIM + d] * u[d * TLEN + t];
    size_t col = (size_t)(t & 15) * 256 + (t >> 4);
    E0[(size_t)r * 4096 + col] = s;
    E0Th[col * ORD + r] = __float2half_rn(s);
}

// ================= mma.sync GEMM (fp16 2-product, batched, opt split-K) ====
#define KC 32
#define STG_B 24576            // Ah 8K | Al 8K | Bh 8K
#define NSTG 4
#define GEMM_SMEM (NSTG * STG_B)  // 96KB; reused as float Cs[128][132]

struct GemmJob {
    const hf *Ah, *Al, *Bh;    // left hi/lo, right (transposed) hi
    int bmul, boff;
    float* C; int ldc;
    hf *Sh, *Sl;               // straight hi/lo pair output
    hf *Th;                    // transposed hi output
    const float* E; int lde, amul, aoff;
    float* outp; int dmul, doff;
    int gx;      // x-tiles (128-col tiles); y-tiles fixed 16
    int kz;      // split-K factor (1 = none)
    float* part; // partials buffer when kz>1
};

__device__ __forceinline__ void load_stage(
    uint32_t st, const hf* __restrict__ Ah, const hf* __restrict__ Al,
    const hf* __restrict__ Bh, size_t arow0, size_t brow0, size_t kb, int tid)
{
#pragma unroll
    for (int q = 0; q < 2; q++) {
        int ch = tid + q * 256;
        int row = ch >> 2, kg = ch & 3;
        uint32_t p = SWZ64((uint32_t)(row * 64 + kg * 16));
        size_t go = (arow0 + row) * ORD + kb + kg * 8;
        cp16(st + p, Ah + go);
        cp16(st + 8192 + p, Al + go);
        size_t gb = (brow0 + row) * ORD + kb + kg * 8;
        cp16(st + 16384 + p, Bh + gb);
    }
}

__device__ void gemm_body(const GemmJob& J, int bx, int by, int z) {
    extern __shared__ char smem[];
    uint32_t sb = smem_u32(smem);
    int tid = threadIdx.x, wid = tid >> 5, lane = tid & 31;
    int bm = by * 128;
    int dblk = bx >> 1, w = (bx & 1) * 128;
    size_t arow0 = (size_t)bm;
    size_t brow0 = (size_t)(J.bmul * dblk + J.boff) * 256 + w;
    size_t kbase = (size_t)z * (ORD / J.kz);
    const int NIT = (ORD / KC) / J.kz;
    int wm = wid >> 2, wn = wid & 3;

    float acc[4][4][4];
#pragma unroll
    for (int i = 0; i < 4; i++)
#pragma unroll
        for (int j = 0; j < 4; j++)
#pragma unroll
            for (int k = 0; k < 4; k++) acc[i][j][k] = 0.f;

    uint32_t a_off[2][4], b_off[2][2];
#pragma unroll
    for (int k16 = 0; k16 < 2; k16++) {
#pragma unroll
        for (int mt = 0; mt < 4; mt++) {
            int row = wm * 64 + mt * 16 + (lane & 15);
            a_off[k16][mt] = SWZ64((uint32_t)(row * 64 + k16 * 32 + (lane >> 4) * 16));
        }
#pragma unroll
        for (int p = 0; p < 2; p++) {
            int n = wn * 32 + p * 16 + ((lane >> 4) & 1) * 8 + (lane & 7);
            b_off[k16][p] = SWZ64((uint32_t)(n * 64 + k16 * 32 + ((lane >> 3) & 1) * 16));
        }
    }

#pragma unroll
    for (int s = 0; s < NSTG - 1; s++) {
        if (s < NIT)
            load_stage(sb + s * STG_B, J.Ah, J.Al, J.Bh,
                       arow0, brow0, kbase + (size_t)s * KC, tid);
        cp_commit();
    }

    int stage = 0;
    for (int t = 0; t < NIT; t++) {
        if (t < NIT - 1) asm volatile("cp.async.wait_group 2;" ::: "memory");
        else             asm volatile("cp.async.wait_group 0;" ::: "memory");
        __syncthreads();

        if (t + NSTG - 1 < NIT) {
            int ns = stage + NSTG - 1; if (ns >= NSTG) ns -= NSTG;
            load_stage(sb + ns * STG_B, J.Ah, J.Al, J.Bh,
                       arow0, brow0, kbase + (size_t)(t + NSTG - 1) * KC, tid);
        }
        cp_commit();

        uint32_t st = sb + stage * STG_B;
#pragma unroll
        for (int k16 = 0; k16 < 2; k16++) {
            uint32_t ah[4][4], al[4][4], bh[2][4];
#pragma unroll
            for (int mt = 0; mt < 4; mt++) {
                ldm_x4(ah[mt], st + a_off[k16][mt]);
                ldm_x4(al[mt], st + 8192 + a_off[k16][mt]);
            }
#pragma unroll
            for (int p = 0; p < 2; p++)
                ldm_x4(bh[p], st + 16384 + b_off[k16][p]);
#pragma unroll
            for (int mt = 0; mt < 4; mt++)
#pragma unroll
                for (int nt = 0; nt < 4; nt++) {
                    const uint32_t* bhp = &bh[nt >> 1][(nt & 1) * 2];
                    mma_f16(acc[mt][nt], ah[mt], bhp);
                    mma_f16(acc[mt][nt], al[mt], bhp);
                }
        }
        stage++; if (stage >= NSTG) stage = 0;
    }
    __syncthreads();   // all MMAs done before smem reuse as Cs

    float (*Cs)[132] = (float (*)[132])smem;
#pragma unroll
    for (int mt = 0; mt < 4; mt++)
#pragma unroll
        for (int nt = 0; nt < 4; nt++) {
            int r = wm * 64 + mt * 16 + (lane >> 2);
            int c = wn * 32 + nt * 8 + 2 * (lane & 3);
            *(float2*)&Cs[r][c]     = make_float2(acc[mt][nt][0], acc[mt][nt][1]);
            *(float2*)&Cs[r + 8][c] = make_float2(acc[mt][nt][2], acc[mt][nt][3]);
        }
    __syncthreads();

    if (J.kz > 1) {
        int row = tid >> 1, off = (tid & 1) * 64;
        int Nw = J.gx * 128;
        float* pp = J.part + ((size_t)z * ORD + bm + row) * Nw + bx * 128 + off;
#pragma unroll
        for (int i = 0; i < 64; i += 4) {
            float4 v4 = *(const float4*)&Cs[row][off + i];
            *(float4*)(pp + i) = v4;
        }
        return;
    }

    int jdst = J.dmul * dblk + J.doff;
    {
        int row = tid >> 1, chb = (tid & 1) * 64;
        int m = bm + row;
#pragma unroll 1
        for (int cb = 0; cb < 4; cb++) {
            int c0 = chb + cb * 16;
            float v[16];
#pragma unroll
            for (int i = 0; i < 16; i++) v[i] = Cs[row][c0 + i];
            if (J.E) {
                const float* ep = J.E + (size_t)m * J.lde
                    + (size_t)(J.amul * dblk + J.aoff) * 256 + w + c0;
#pragma unroll
                for (int i = 0; i < 16; i += 4) {
                    float4 e4 = *(const float4*)(ep + i);
                    v[i] += e4.x; v[i+1] += e4.y; v[i+2] += e4.z; v[i+3] += e4.w;
                }
#pragma unroll
                for (int i = 0; i < 16; i++) Cs[row][c0 + i] = v[i];
            }
            if (J.C) {
                float* cp = J.C + (size_t)m * J.ldc + (size_t)jdst * 256 + w + c0;
#pragma unroll
                for (int i = 0; i < 16; i += 4)
                    *(float4*)(cp + i) = make_float4(v[i], v[i+1], v[i+2], v[i+3]);
            }
            if (J.Sh) {
                hf* sp = J.Sh + (size_t)m * ORD + (size_t)jdst * 256 + w + c0;
                hf* lp = J.Sl + (size_t)m * ORD + (size_t)jdst * 256 + w + c0;
#pragma unroll
                for (int i = 0; i < 16; i++) {
                    hf hi = __float2half_rn(v[i]);
                    sp[i] = hi;
                    lp[i] = __float2half_rn(v[i] - __half2float(hi));
                }
            }
            if (J.outp) {
                float* op = J.outp + (size_t)m * TLEN + jdst;
#pragma unroll
                for (int i = 0; i < 16; i++)
                    op[(w + c0 + i) * 16] = tanhf(v[i]);
            }
        }
    }
    if (J.Th) {
        __syncthreads();
        int n = tid >> 1, mh = (tid & 1) * 64;
        size_t trow = (size_t)jdst * 256 + w + n;
        hf* tp = J.Th + trow * ORD + bm + mh;
#pragma unroll 1
        for (int cb = 0; cb < 4; cb++) {
#pragma unroll
            for (int i = 0; i < 16; i++)
                tp[cb * 16 + i] = __float2half_rn(Cs[mh + cb * 16 + i][n]);
        }
    }
}

__global__ void __launch_bounds__(256, 2) gemm_batch(GemmJob j0, GemmJob j1, int n0) {
    int bid = blockIdx.x;
    const GemmJob& J = (bid < n0) ? j0 : j1;
    int lid = (bid < n0) ? bid : bid - n0;
    int bx = lid % J.gx;
    int r = lid / J.gx;
    gemm_body(J, bx, r & 15, r >> 4);
}

// ================= split-K reduce with fused downsweep epilogue ============
__global__ void __launch_bounds__(256) reduce_ds(
    const float* __restrict__ part, int N, int kz,
    const float* __restrict__ E, int lde, int amul, int aoff,
    hf* __restrict__ Th, float* __restrict__ outp, int dmul, int doff)
{
    __shared__ float ts[64][65];
    int bm = blockIdx.y * 64, bn = blockIdx.x * 64;
    int tid = threadIdx.x;
    int dblk = bn >> 8;
    int jdst = dmul * dblk + doff;

    int r = tid >> 2, c0 = (tid & 3) * 16;
    int m = bm + r;
    float v[16];
    {
        const float* ep = E + (size_t)m * lde + (size_t)(amul * dblk + aoff) * 256
                        + (bn & 255) + c0;
#pragma unroll
        for (int i = 0; i < 16; i += 4) {
            float4 e4 = *(const float4*)(ep + i);
            v[i] = e4.x; v[i+1] = e4.y; v[i+2] = e4.z; v[i+3] = e4.w;
        }
    }
    for (int z = 0; z < kz; z++) {
        const float* pp = part + ((size_t)z * ORD + m) * N + bn + c0;
#pragma unroll
        for (int i = 0; i < 16; i += 4) {
            float4 p4 = *(const float4*)(pp + i);
            v[i] += p4.x; v[i+1] += p4.y; v[i+2] += p4.z; v[i+3] += p4.w;
        }
    }
    {
        float* op = outp + (size_t)m * TLEN + jdst;
#pragma unroll
        for (int i = 0; i < 16; i++)
            op[((bn & 255) + c0 + i) * 16] = tanhf(v[i]);
    }
#pragma unroll
    for (int i = 0; i < 16; i++) ts[r][c0 + i] = v[i];
    __syncthreads();

    int cc = tid >> 2, r0 = (tid & 3) * 16;
    size_t trow = (size_t)jdst * 256 + (bn & 255) + cc;
    hf* tp = Th + trow * ORD + bm + r0;
#pragma unroll
    for (int i = 0; i < 16; i++)
        tp[i] = __float2half_rn(ts[r0 + i][cc]);
}

// ================= persistent boundary scan =================
__global__ void __launch_bounds__(256, 1) scan_kernel(
    const float* __restrict__ A16, const float* __restrict__ D,
    hf* __restrict__ STh, float* __restrict__ outp)
{
    __shared__ float bs[ORD];
    __shared__ float red[16][9];

    int tid = threadIdx.x;
    int cta = blockIdx.x;                 // 128 CTAs, 16 rows each
    int rloc = tid & 15;
    int row = cta * 16 + rloc;
    int seg = (tid >> 4) * 128;

    ulonglong2 a2[32];
    const ulonglong2* Arow = (const ulonglong2*)(A16 + (size_t)row * ORD + seg);
#pragma unroll
    for (int i = 0; i < 32; i++) a2[i] = Arow[i];

    for (int i = tid; i < ORD; i += 256) g_bv[i] = 1.0f;
    if (tid < 16) {
        int rr = cta * 16 + tid;
        STh[rr] = __float2half_rn(1.0f);
        outp[(size_t)rr * TLEN] = tanhf(1.0f);
    }
    if (tid == 0) {
        g_flags[cta] = 0u;
        if (cta == 0) g_gen2 = 0u;
    }
    grid_barrier(128);

    for (int c = 0; c < NC - 1; c++) {
        const float4* bsrc = (const float4*)(g_bv + (c & 1) * ORD);
        float4* bdst4 = (float4*)bs;
        bdst4[tid] = bsrc[tid];
        bdst4[tid + 256] = bsrc[tid + 256];
        float dval = 0.f;
        if (tid < 16) dval = D[(size_t)(cta * 16 + tid) * 256 + c];
        __syncthreads();

        ull pA = 0ull, pB = 0ull;
        const ulonglong2* b2 = (const ulonglong2*)(bs + seg);
#pragma unroll
        for (int i = 0; i < 32; i++) {
            pA = fma2(a2[i].x, b2[i].x, pA);
            pB = fma2(a2[i].y, b2[i].y, pB);
        }
        float2 fa = unpk(pA), fb = unpk(pB);
        float p = (fa.x + fa.y) + (fb.x + fb.y);
        p += __shfl_down_sync(0xffffffffu, p, 16);
        if ((tid & 31) < 16) red[rloc][tid >> 5] = p;
        __syncthreads();

        if (tid < 16) {
            int rr = cta * 16 + tid;
            float s = red[tid][0] + red[tid][1] + red[tid][2] + red[tid][3]
                    + red[tid][4] + red[tid][5] + red[tid][6] + red[tid][7]
                    + dval;
            g_bv[((c + 1) & 1) * ORD + rr] = s;
            STh[(size_t)(c + 1) * ORD + rr] = __float2half_rn(s);
            outp[(size_t)rr * TLEN + (c + 1) * 16] = tanhf(s);
        }

        // ---- contention-free flag barrier ----
        unsigned int it = (unsigned int)(c + 1);
        __syncthreads();
        if (cta == 0) {
            if (tid >= 1 && tid < 128) {
                unsigned int fv;
                do { fv = g_flags[tid]; } while (fv < it);
            }
            __syncthreads();
            if (tid == 0) { __threadfence(); g_gen2 = it; __threadfence(); }
            __syncthreads();
        } else {
            if (tid == 0) {
                __threadfence();
                g_flags[cta] = it;
                unsigned int gv;
                do { __nanosleep(16); gv = g_gen2; } while (gv < it);
                __threadfence();
            }
            __syncthreads();
        }
    }
}

// ================= host orchestration =================
static GemmJob mkjob(const hf* Ah, const hf* Al, const hf* Bh,
                     int bmul, int boff, float* C, int ldc,
                     hf* Sh, hf* Sl, hf* Th,
                     const float* E, int lde, int amul, int aoff,
                     float* outp, int dmul, int doff, int gx, int kz, float* part) {
    GemmJob j;
    j.Ah = Ah; j.Al = Al; j.Bh = Bh;
    j.bmul = bmul; j.boff = boff; j.C = C; j.ldc = ldc;
    j.Sh = Sh; j.Sl = Sl; j.Th = Th;
    j.E = E; j.lde = lde; j.amul = amul; j.aoff = aoff;
    j.outp = outp; j.dmul = dmul; j.doff = doff; j.gx = gx;
    j.kz = kz; j.part = part;
    return j;
}

extern "C" void kernel_launch(void* const* d_in, const int* in_sizes, int n_in,
                              void* d_out, int out_size) {
    const float* u = 0; const float* wa = 0; const float* wb = 0;
    for (int i = 0; i < n_in; i++) {
        if (in_sizes[i] == INDIM * TLEN)       u  = (const float*)d_in[i];
        else if (in_sizes[i] == ORD * ORD)     wa = (const float*)d_in[i];
        else if (in_sizes[i] == ORD * INDIM)   wb = (const float*)d_in[i];
    }
    float* out = (float*)d_out;

    hf *Ah, *Al, *ATh;
    hf *Q2h, *Q2l, *Q2Th, *Q4h, *Q4l, *Q4Th, *Q8h, *Q8l, *Q8Th;
    hf *E0Th, *E1Th, *E2Th, *E3Th, *STh;
    float *Q16, *E0, *E1, *E2, *E3, *Dv, *Part;
    cudaGetSymbolAddress((void**)&Ah, g_Ah);   cudaGetSymbolAddress((void**)&Al, g_Al);
    cudaGetSymbolAddress((void**)&ATh, g_ATh);
    cudaGetSymbolAddress((void**)&Q2h, g_Q2h); cudaGetSymbolAddress((void**)&Q2l, g_Q2l);
    cudaGetSymbolAddress((void**)&Q2Th, g_Q2Th);
    cudaGetSymbolAddress((void**)&Q4h, g_Q4h); cudaGetSymbolAddress((void**)&Q4l, g_Q4l);
    cudaGetSymbolAddress((void**)&Q4Th, g_Q4Th);
    cudaGetSymbolAddress((void**)&Q8h, g_Q8h); cudaGetSymbolAddress((void**)&Q8l, g_Q8l);
    cudaGetSymbolAddress((void**)&Q8Th, g_Q8Th);
    cudaGetSymbolAddress((void**)&Q16, g_Q16);
    cudaGetSymbolAddress((void**)&E0, g_E0);
    cudaGetSymbolAddress((void**)&E0Th, g_E0Th);
    cudaGetSymbolAddress((void**)&E1, g_E1);
    cudaGetSymbolAddress((void**)&E1Th, g_E1Th);
    cudaGetSymbolAddress((void**)&E2, g_E2);
    cudaGetSymbolAddress((void**)&E2Th, g_E2Th);
    cudaGetSymbolAddress((void**)&E3, g_E3);
    cudaGetSymbolAddress((void**)&E3Th, g_E3Th);
    cudaGetSymbolAddress((void**)&Dv, g_D);
    cudaGetSymbolAddress((void**)&STh, g_STh);
    cudaGetSymbolAddress((void**)&Part, g_part);

    cudaFuncSetAttribute(gemm_batch, cudaFuncAttributeMaxDynamicSharedMemorySize, GEMM_SMEM);

    // conversions of wa + BU precompute
    conv_straight<<<ORD * ORD / 256, 256>>>(wa, Ah, Al);
    conv_transpose<<<dim3(64, 64), dim3(32, 8)>>>(wa, ATh);
    bu_kernel<<<dim3(TLEN / 32, ORD / 8), dim3(32, 8)>>>(wb, u, E0, E0Th);

    // jobs
    GemmJob jQ2  = mkjob(Ah, Al, ATh, 1, 0, 0, 0, Q2h, Q2l, Q2Th,
                         0, 0, 0, 0, 0, 1, 0, 16, 1, 0);
    GemmJob jE1  = mkjob(Ah, Al, E0Th, 2, 0, E1, 2048, 0, 0, E1Th,
                         E0, 4096, 2, 1, 0, 1, 0, 16, 1, 0);
    GemmJob jQ4  = mkjob(Q2h, Q2l, Q2Th, 1, 0, 0, 0, Q4h, Q4l, Q4Th,
                         0, 0, 0, 0, 0, 1, 0, 16, 1, 0);
    GemmJob jE2  = mkjob(Q2h, Q2l, E1Th, 2, 0, E2, 1024, 0, 0, E2Th,
                         E1, 2048, 2, 1, 0, 1, 0, 8, 1, 0);
    GemmJob jQ8  = mkjob(Q4h, Q4l, Q4Th, 1, 0, 0, 0, Q8h, Q8l, Q8Th,
                         0, 0, 0, 0, 0, 1, 0, 16, 1, 0);
    GemmJob jE3  = mkjob(Q4h, Q4l, E2Th, 2, 0, E3, 512, 0, 0, E3Th,
                         E2, 1024, 2, 1, 0, 1, 0, 4, 1, 0);
    GemmJob jQ16 = mkjob(Q8h, Q8l, Q8Th, 1, 0, Q16, ORD, 0, 0, 0,
                         0, 0, 0, 0, 0, 1, 0, 16, 1, 0);
    GemmJob jD   = mkjob(Q8h, Q8l, E3Th, 2, 0, Dv, 256, 0, 0, 0,
                         E3, 512, 2, 1, 0, 1, 0, 2, 1, 0);
    // downsweep: S8/S4/S2 split-K (partials + fused reduce), S1 direct
    GemmJob jS8  = mkjob(Q8h, Q8l, STh, 1, 0, 0, 0, 0, 0, 0,
                         0, 0, 0, 0, 0, 0, 8, 2, 8, Part);
    GemmJob jS4  = mkjob(Q4h, Q4l, STh, 8, 0, 0, 0, 0, 0, 0,
                         0, 0, 0, 0, 0, 8, 4, 4, 4, Part);
    GemmJob jS2  = mkjob(Q2h, Q2l, STh, 4, 0, 0, 0, 0, 0, 0,
                         0, 0, 0, 0, 0, 4, 2, 8, 2, Part);
    GemmJob jS1  = mkjob(Ah, Al, STh, 2, 0, 0, 0, 0, 0, 0,
                         E0, 4096, 2, 0, out, 2, 1, 16, 1, 0);

    // level-batched: squaring chain || upsweep chain (independent within level)
    gemm_batch<<<256 + 256, 256, GEMM_SMEM>>>(jQ2, jE1, 256);
    gemm_batch<<<256 + 128, 256, GEMM_SMEM>>>(jQ4, jE2, 256);
    gemm_batch<<<256 + 64, 256, GEMM_SMEM>>>(jQ8, jE3, 256);
    gemm_batch<<<256 + 32, 256, GEMM_SMEM>>>(jQ16, jD, 256);

    // serial boundary scan (emits j=0, fills ST block 0)
    scan_kernel<<<128, 256>>>(Q16, Dv, STh, out);

    // downsweep (serial chain; split-K levels + fused reduce)
    gemm_batch<<<256, 256, GEMM_SMEM>>>(jS8, jS8, 256);          // 2*16*8
    reduce_ds<<<dim3(4, 32), 256>>>(Part, 256, 8, E3, 512, 2, 0,
                                    STh, out, 0, 8);
    gemm_batch<<<256, 256, GEMM_SMEM>>>(jS4, jS4, 256);          // 4*16*4
    reduce_ds<<<dim3(8, 32), 256>>>(Part, 512, 4, E2, 1024, 2, 0,
                                    STh, out, 8, 4);
    gemm_batch<<<256, 256, GEMM_SMEM>>>(jS2, jS2, 256);          // 8*16*2
    reduce_ds<<<dim3(16, 32), 256>>>(Part, 1024, 2, E1, 2048, 2, 0,
                                     STh, out, 4, 2);
    gemm_batch<<<256, 256, GEMM_SMEM>>>(jS1, jS1, 256);
}